// round 11
// baseline (speedup 1.0000x reference)
#include <cuda_runtime.h>
#include <math.h>
#include <cstdint>

#define NGRAPH 1024
#define TOPK 32
#define BS 256
#define NBLK 2048
#define QCAP 1024                            // per-block smem hit queue
#define CAP2 512                             // per-graph global candidate cap
#define CAP 2048                             // fallback smem cap
#define CHUNK_F 4096                         // 16 KB fill chunk (floats)
#define NEG_MIN (-3.4028234663852886e38f)    // np.finfo(float32).min == -FLT_MAX
#define THR 2.0f                             // prior threshold ~2 sigma

__device__ unsigned g_cand_fl[NGRAPH * CAP2];
__device__ int      g_cand_ix[NGRAPH * CAP2];
__device__ int      g_cand_cnt[NGRAPH];      // zero-init; rank_kernel re-zeros

// Order-preserving float->uint flip: larger float -> larger unsigned.
__device__ __forceinline__ unsigned flipf(float s) {
    unsigned u = __float_as_uint(s);
    return (u & 0x80000000u) ? ~u : (u | 0x80000000u);
}

__device__ __forceinline__ uint32_t smem_u32(const void* p) {
    uint32_t a;
    asm("{ .reg .u64 t; cvta.to.shared.u64 t, %1; cvt.u32.u64 %0, t; }"
        : "=r"(a) : "l"(p));
    return a;
}

__device__ __forceinline__ void push_direct(
    const int* __restrict__ cmask, const int* __restrict__ b32,
    bool is64, int idx, float s)
{
    if (cmask[idx]) {
        const int gph = is64 ? (int)((const long long*)b32)[idx] : b32[idx];
        const int p   = atomicAdd(&g_cand_cnt[gph], 1);
        if (p < CAP2) {
            g_cand_fl[gph * CAP2 + p] = flipf(s);
            g_cand_ix[gph * CAP2 + p] = idx;
        }
    }
}

// ---------------------------------------------------------------------------
// K1: streaming scan. The 64MB NEG_MIN fill is issued as async TMA bulk
// stores (smem pattern tile -> gmem) BEFORE the scan loop, so the warps run a
// PURE-READ score stream. Threshold hits go to a per-block smem queue; a
// drain phase loads cmask for the hits in parallel and pushes survivors to
// the owning graph's global candidate list.
// ---------------------------------------------------------------------------
__global__ void __launch_bounds__(BS) scan_kernel(
    const float* __restrict__ scores,
    const int*   __restrict__ cmask,        // bool delivered as int32
    const int*   __restrict__ b32,          // edge_batch (int32 or int64 words)
    float* __restrict__ out,
    int E)
{
    __shared__ int   q_cnt;
    __shared__ float q_sc[QCAP];
    __shared__ int   q_ix[QCAP];
    __shared__ __align__(16) float pat[CHUNK_F];   // 16 KB fill pattern

    const int  nv   = E >> 2;
    const int  gid  = blockIdx.x * BS + threadIdx.x;
    const int  gsz  = NBLK * BS;
    const bool is64 = (b32[(E - 2) | 1] == 0);   // dtype sniff (L1-broadcast)

    // ---- Prepare pattern + issue all async fill stores for this block ----
    for (int i = threadIdx.x; i < CHUNK_F; i += BS) pat[i] = NEG_MIN;
    if (threadIdx.x == 0) q_cnt = 0;
    __syncthreads();

    const int nchunks = E / CHUNK_F;             // full 16KB chunks
    if (threadIdx.x == 0) {
        asm volatile("fence.proxy.async.shared::cta;" ::: "memory");
        const uint32_t ps = smem_u32(pat);
        for (int c = blockIdx.x; c < nchunks; c += NBLK) {
            asm volatile(
                "cp.async.bulk.global.shared::cta.bulk_group [%0], [%1], %2;"
                :: "l"(out + (size_t)c * CHUNK_F), "r"(ps), "r"(CHUNK_F * 4)
                : "memory");
        }
        asm volatile("cp.async.bulk.commit_group;" ::: "memory");
    }
    // scalar fill of the tail region beyond the last full chunk
    if (blockIdx.x == 0) {
        for (int i = nchunks * CHUNK_F + threadIdx.x; i < E; i += BS)
            out[i] = NEG_MIN;
    }

    // ---- Hot loop: pure read stream + smem-queue push ----
    const float4* sc4 = (const float4*)scores;
    #pragma unroll 8
    for (int v = gid; v < nv; v += gsz) {
        const float4 sc = __ldcs(sc4 + v);
        const float  mx = fmaxf(fmaxf(sc.x, sc.y), fmaxf(sc.z, sc.w));
        if (mx > THR) {
            const int i = v << 2;
            #pragma unroll
            for (int w = 0; w < 4; ++w) {
                const float s = (w == 0) ? sc.x : (w == 1) ? sc.y : (w == 2) ? sc.z : sc.w;
                if (s > THR) {
                    const int p = atomicAdd(&q_cnt, 1);
                    if (p < QCAP) { q_sc[p] = s; q_ix[p] = i + w; }
                    else          push_direct(cmask, b32, is64, i + w, s);  // overflow (never in practice)
                }
            }
        }
    }
    // scalar score tail (E % 4)
    if (blockIdx.x == 0) {
        for (int i = (nv << 2) + threadIdx.x; i < E; i += BS) {
            const float s = scores[i];
            if (s > THR) {
                const int p = atomicAdd(&q_cnt, 1);
                if (p < QCAP) { q_sc[p] = s; q_ix[p] = i; }
                else          push_direct(cmask, b32, is64, i, s);
            }
        }
    }
    __syncthreads();

    // ---- Drain: parallel mask filter + global push ----
    const int n = min(q_cnt, QCAP);
    for (int j = threadIdx.x; j < n; j += BS) {
        const int idx = q_ix[j];
        if (cmask[idx]) {
            const int gph = is64 ? (int)((const long long*)b32)[idx] : b32[idx];
            const int p   = atomicAdd(&g_cand_cnt[gph], 1);
            if (p < CAP2) {
                g_cand_fl[gph * CAP2 + p] = flipf(q_sc[j]);
                g_cand_ix[gph * CAP2 + p] = idx;
            }
        }
    }

    // ---- Ensure all async fill stores are complete before kernel exit ----
    if (threadIdx.x == 0)
        asm volatile("cp.async.bulk.wait_group 0;" ::: "memory");
}

// ---------------------------------------------------------------------------
// K2: per-graph exact top-K from the candidate list via byte-radix select in
// smem (stable tie-break: score desc, index asc); segmented log-denominator;
// kept writes. Exact gmem radix fallback when the list is unusable.
// ---------------------------------------------------------------------------
__global__ void __launch_bounds__(BS) rank_kernel(
    const float* __restrict__ logits,
    const float* __restrict__ scores,
    const float* __restrict__ stop,
    const int*   __restrict__ cmask,
    const int*   __restrict__ b32,
    float* __restrict__ out,
    int E)
{
    __shared__ unsigned buf_fl[CAP];
    __shared__ int      buf_ix[CAP];
    __shared__ unsigned tb_fl[CAP2];
    __shared__ int      tb_ix[CAP2];
    __shared__ int      s_kidx[TOPK];
    __shared__ float    s_lv[TOPK];
    __shared__ float    s_ld;
    __shared__ int      seg[2];
    __shared__ int      hist[2048];
    __shared__ int      s_found, s_bin, s_above, s_minix, s_kcnt;
    __shared__ unsigned s_Tf;
    __shared__ int      s_Tix;

    const int g   = blockIdx.x;
    const int tid = threadIdx.x;
    const int cnt = g_cand_cnt[g];

    int kc;
    if (cnt >= TOPK && cnt <= CAP2) {
        // ---- Fast path: byte-radix select over the smem candidate list ----
        for (int j = tid; j < cnt; j += BS) {
            buf_fl[j] = g_cand_fl[g * CAP2 + j];
            buf_ix[j] = g_cand_ix[g * CAP2 + j];
        }
        __syncthreads();

        unsigned prefix = 0, pmask = 0;
        int above = 0;
        for (int lvl = 0; lvl < 4; ++lvl) {
            const int shift = 24 - 8 * lvl;
            if (tid < 256) hist[tid] = 0;
            __syncthreads();
            for (int j = tid; j < cnt; j += BS) {
                const unsigned fl = buf_fl[j];
                if ((fl & pmask) == prefix)
                    atomicAdd(&hist[(fl >> shift) & 0xFF], 1);
            }
            __syncthreads();

            if (tid < 32) {
                const int lane = tid;
                const int Kp   = TOPK - above;
                int cum = 0;
                for (int base = 255; base >= 0; base -= 32) {
                    int bin = base - lane;
                    int c   = hist[bin];
                    int incl = c;
                    #pragma unroll
                    for (int off = 1; off < 32; off <<= 1) {
                        int v = __shfl_up_sync(0xffffffffu, incl, off);
                        if (lane >= off) incl += v;
                    }
                    unsigned bal = __ballot_sync(0xffffffffu, cum + incl >= Kp);
                    if (bal) {
                        int first = __ffs(bal) - 1;
                        if (lane == first) { s_bin = bin; s_above = cum + incl - c; }
                        break;
                    }
                    cum += __shfl_sync(0xffffffffu, incl, 31);
                }
            }
            __syncthreads();

            const int b = s_bin;
            const int n = hist[b];
            above  += s_above;
            prefix |= ((unsigned)b) << shift;
            pmask  |= 0xFFu << shift;
            __syncthreads();                    // hist reads done

            if (n <= 64 || lvl == 3) {
                if (tid == 0) s_kcnt = 0;
                __syncthreads();
                for (int j = tid; j < cnt; j += BS) {
                    const unsigned fl = buf_fl[j];
                    if ((fl & pmask) == prefix) {
                        int p = atomicAdd(&s_kcnt, 1);
                        tb_fl[p] = fl; tb_ix[p] = buf_ix[j];
                    }
                }
                __syncthreads();
                const int nn = s_kcnt;
                const int r  = TOPK - 1 - above;
                for (int j = tid; j < nn; j += BS) {
                    const unsigned fj = tb_fl[j];
                    const int      ij = tb_ix[j];
                    int rk = 0;
                    for (int l = 0; l < nn; ++l) {
                        const unsigned fl2 = tb_fl[l];
                        rk += (fl2 > fj) || (fl2 == fj && tb_ix[l] < ij);
                    }
                    if (rk == r) { s_Tf = fj; s_Tix = ij; }
                }
                __syncthreads();
                break;
            }
        }

        const unsigned Tf = s_Tf; const int Tix = s_Tix;
        if (tid == 0) s_kcnt = 0;
        __syncthreads();
        for (int j = tid; j < cnt; j += BS) {
            const unsigned fl = buf_fl[j];
            if (fl > Tf || (fl == Tf && buf_ix[j] <= Tix)) {
                int p = atomicAdd(&s_kcnt, 1);
                s_kidx[p] = buf_ix[j];
            }
        }
        kc = TOPK;
        __syncthreads();
    } else {
        // ---- Fallback: segment bounds + exact 3-level radix over gmem ----
        if (tid < 2) {
            const int target = g + tid;
            int lo = 0;
            if (target == NGRAPH) lo = E;
            else if (target > 0) {
                const bool is64 = (b32[(E - 2) | 1] == 0);
                int hi = E;
                if (is64) {
                    const long long* b = (const long long*)b32;
                    const long long key = (long long)target;
                    while (lo < hi) { int mid = (lo + hi) >> 1; if (b[mid] < key) lo = mid + 1; else hi = mid; }
                } else {
                    while (lo < hi) { int mid = (lo + hi) >> 1; if (b32[mid] < target) lo = mid + 1; else hi = mid; }
                }
            }
            seg[tid] = lo;
        }
        __syncthreads();
        const int s0 = seg[0], s1 = seg[1];

        unsigned prefix = 0, pmask = 0;
        int  above = 0;
        bool keepall = false, have_thr = false;

        for (int lvl = 0; lvl < 3; ++lvl) {
            const int      shift = (lvl == 0) ? 21 : (lvl == 1) ? 10 : 0;
            const unsigned mw    = (lvl == 2) ? 0x3FFu : 0x7FFu;

            for (int j = tid; j < 2048; j += BS) hist[j] = 0;
            if (tid == 0) s_found = 0;
            __syncthreads();

            for (int i = s0 + tid; i < s1; i += BS) {
                if (cmask[i] != 0) {
                    unsigned fl = flipf(scores[i]);
                    if ((fl & pmask) == prefix)
                        atomicAdd(&hist[(fl >> shift) & mw], 1);
                }
            }
            __syncthreads();

            if (tid < 32) {
                const int lane = tid;
                const int Kp   = TOPK - above;
                int cum = 0;
                for (int base = (int)mw; base >= 0; base -= 32) {
                    int bin = base - lane;
                    int c   = (bin >= 0) ? hist[bin] : 0;
                    int incl = c;
                    #pragma unroll
                    for (int off = 1; off < 32; off <<= 1) {
                        int v = __shfl_up_sync(0xffffffffu, incl, off);
                        if (lane >= off) incl += v;
                    }
                    unsigned bal = __ballot_sync(0xffffffffu, cum + incl >= Kp);
                    if (bal) {
                        int first = __ffs(bal) - 1;
                        if (lane == first) { s_bin = bin; s_above = cum + incl - c; s_found = 1; }
                        break;
                    }
                    cum += __shfl_sync(0xffffffffu, incl, 31);
                }
            }
            __syncthreads();

            if (!s_found) { keepall = true; break; }

            const int b = s_bin;
            above  += s_above;
            const int n = hist[b];
            prefix |= ((unsigned)b) << shift;
            pmask  |= mw << shift;
            __syncthreads();

            if (n <= CAP) {
                if (tid == 0) s_kcnt = 0;
                __syncthreads();
                for (int i = s0 + tid; i < s1; i += BS) {
                    if (cmask[i] != 0) {
                        unsigned fl = flipf(scores[i]);
                        if ((fl & pmask) == prefix) {
                            int p = atomicAdd(&s_kcnt, 1);
                            buf_fl[p] = fl; buf_ix[p] = i;
                        }
                    }
                }
                __syncthreads();
                const int nn = s_kcnt;
                const int r  = TOPK - 1 - above;
                for (int j = tid; j < nn; j += BS) {
                    unsigned fj = buf_fl[j]; int ij = buf_ix[j];
                    int rk = 0;
                    for (int l = 0; l < nn; ++l) {
                        unsigned fl2 = buf_fl[l];
                        rk += (fl2 > fj) || (fl2 == fj && buf_ix[l] < ij);
                    }
                    if (rk == r) { s_Tf = fj; s_Tix = ij; }
                }
                have_thr = true;
                __syncthreads();
                break;
            }
        }

        unsigned Tf; int Tix;
        if (keepall)       { Tf = 0u;   Tix = 0x7FFFFFFF; }
        else if (have_thr) { Tf = s_Tf; Tix = s_Tix; }
        else {
            const int m = TOPK - above;
            int last = -1;
            for (int t = 0; t < m; ++t) {
                if (tid == 0) s_minix = 0x7FFFFFFF;
                __syncthreads();
                for (int i = s0 + tid; i < s1; i += BS) {
                    if (cmask[i] != 0 && i > last) {
                        if (flipf(scores[i]) == prefix) atomicMin(&s_minix, i);
                    }
                }
                __syncthreads();
                last = s_minix;
                __syncthreads();
            }
            Tf = prefix; Tix = last;
        }

        if (tid == 0) s_kcnt = 0;
        __syncthreads();
        for (int i = s0 + tid; i < s1; i += BS) {
            if (cmask[i] != 0) {
                unsigned fl = flipf(scores[i]);
                if (fl > Tf || (fl == Tf && i <= Tix)) {
                    int p = atomicAdd(&s_kcnt, 1);
                    if (p < TOPK) s_kidx[p] = i;
                }
            }
        }
        __syncthreads();
        kc = min(s_kcnt, TOPK);
    }

    // ---- Segmented log-denominator over the <=32 kept logits + stop ----
    if (tid < kc) s_lv[tid] = logits[s_kidx[tid]];   // TEMP == 1.0
    __syncthreads();

    if (tid < 32) {
        float v = (tid < kc) ? s_lv[tid] : -INFINITY;
        float mx = v;
        #pragma unroll
        for (int off = 16; off; off >>= 1) mx = fmaxf(mx, __shfl_xor_sync(0xffffffffu, mx, off));
        float e = (tid < kc) ? expf(v - mx) : 0.0f;
        #pragma unroll
        for (int off = 16; off; off >>= 1) e += __shfl_xor_sync(0xffffffffu, e, off);
        if (tid == 0) {
            float st = stop[g];
            float ld;
            if (kc == 0) ld = st;
            else {
                float lse = logf(e) + mx;
                float a = fmaxf(lse, st), b2 = fminf(lse, st);
                ld = a + log1pf(expf(b2 - a));
            }
            s_ld = ld;
        }
    }
    __syncthreads();

    if (tid < kc) out[s_kidx[tid]] = s_lv[tid] - s_ld;

    // Reset this graph's counter for the next (graph-replayed) run.
    if (tid == 0) g_cand_cnt[g] = 0;
}

extern "C" void kernel_launch(void* const* d_in, const int* in_sizes, int n_in,
                              void* d_out, int out_size) {
    const float* logits = (const float*)d_in[0];
    const float* scores = (const float*)d_in[1];
    const float* stop   = (const float*)d_in[2];
    const int*   batch  = (const int*)d_in[3];
    const int*   cmask  = (const int*)d_in[4];
    float* out = (float*)d_out;
    const int E = in_sizes[0];

    scan_kernel<<<NBLK, BS>>>(scores, cmask, batch, out, E);
    rank_kernel<<<NGRAPH, BS>>>(logits, scores, stop, cmask, batch, out, E);
}

// round 12
// speedup vs baseline: 1.0200x; 1.0200x over previous
#include <cuda_runtime.h>
#include <math.h>
#include <cstdint>

#define NGRAPH 1024
#define TOPK 32
#define BS 256
#define NBLK 2048
#define QCAP 1024                            // per-block smem hit queue
#define CAP2 512                             // per-graph global candidate cap
#define CAP 2048                             // fallback smem cap
#define CHUNK_F 4096                         // 16 KB fill chunk (floats)
#define NEG_MIN (-3.4028234663852886e38f)    // np.finfo(float32).min == -FLT_MAX
#define THR 2.0f                             // prior threshold ~2 sigma

__device__ unsigned g_cand_fl[NGRAPH * CAP2];
__device__ int      g_cand_ix[NGRAPH * CAP2];
__device__ int      g_cand_cnt[NGRAPH];      // zero-init; rank_kernel re-zeros

// Order-preserving float->uint flip: larger float -> larger unsigned.
__device__ __forceinline__ unsigned flipf(float s) {
    unsigned u = __float_as_uint(s);
    return (u & 0x80000000u) ? ~u : (u | 0x80000000u);
}

__device__ __forceinline__ uint32_t smem_u32(const void* p) {
    uint32_t a;
    asm("{ .reg .u64 t; cvta.to.shared.u64 t, %1; cvt.u32.u64 %0, t; }"
        : "=r"(a) : "l"(p));
    return a;
}

__device__ __forceinline__ void push_direct(
    const int* __restrict__ cmask, const int* __restrict__ b32,
    bool is64, int idx, float s)
{
    if (cmask[idx]) {
        const int gph = is64 ? (int)((const long long*)b32)[idx] : b32[idx];
        const int p   = atomicAdd(&g_cand_cnt[gph], 1);
        if (p < CAP2) {
            g_cand_fl[gph * CAP2 + p] = flipf(s);
            g_cand_ix[gph * CAP2 + p] = idx;
        }
    }
}

// ---------------------------------------------------------------------------
// K1: streaming scan. Phase 1 is a PURE-READ score stream (LSU floor: only
// LDGs in the warp instruction stream); threshold hits go to a per-block smem
// queue. Phase 2 issues the 64MB NEG_MIN fill as async TMA bulk stores
// (AFTER the read loop, so writes never sit in front of the latency-bound
// LDG stream). Phase 3 drains the queue (parallel cmask filter + global
// push) while TMA writes complete; wait_group comes last.
// ---------------------------------------------------------------------------
__global__ void __launch_bounds__(BS) scan_kernel(
    const float* __restrict__ scores,
    const int*   __restrict__ cmask,        // bool delivered as int32
    const int*   __restrict__ b32,          // edge_batch (int32 or int64 words)
    float* __restrict__ out,
    int E)
{
    __shared__ int   q_cnt;
    __shared__ float q_sc[QCAP];
    __shared__ int   q_ix[QCAP];
    __shared__ __align__(16) float pat[CHUNK_F];   // 16 KB fill pattern

    const int  nv   = E >> 2;
    const int  gid  = blockIdx.x * BS + threadIdx.x;
    const int  gsz  = NBLK * BS;
    const bool is64 = (b32[(E - 2) | 1] == 0);   // dtype sniff (L1-broadcast)

    // Prepare fill pattern tile + queue counter.
    for (int i = threadIdx.x; i < CHUNK_F; i += BS) pat[i] = NEG_MIN;
    if (threadIdx.x == 0) q_cnt = 0;
    __syncthreads();

    // ---- Phase 1: pure read stream + smem-queue push ----
    const float4* sc4 = (const float4*)scores;
    #pragma unroll 4
    for (int v = gid; v < nv; v += gsz) {
        const float4 sc = __ldcs(sc4 + v);
        const float  mx = fmaxf(fmaxf(sc.x, sc.y), fmaxf(sc.z, sc.w));
        if (mx > THR) {
            const int i = v << 2;
            #pragma unroll
            for (int w = 0; w < 4; ++w) {
                const float s = (w == 0) ? sc.x : (w == 1) ? sc.y : (w == 2) ? sc.z : sc.w;
                if (s > THR) {
                    const int p = atomicAdd(&q_cnt, 1);
                    if (p < QCAP) { q_sc[p] = s; q_ix[p] = i + w; }
                    else          push_direct(cmask, b32, is64, i + w, s);  // overflow (never in practice)
                }
            }
        }
    }
    // scalar score tail (E % 4)
    if (blockIdx.x == 0) {
        for (int i = (nv << 2) + threadIdx.x; i < E; i += BS) {
            const float s = scores[i];
            if (s > THR) {
                const int p = atomicAdd(&q_cnt, 1);
                if (p < QCAP) { q_sc[p] = s; q_ix[p] = i; }
                else          push_direct(cmask, b32, is64, i, s);
            }
        }
    }
    __syncthreads();

    // ---- Phase 2: async TMA bulk fill of this block's output chunks ----
    const int nchunks = E / CHUNK_F;             // full 16KB chunks
    if (threadIdx.x == 0) {
        asm volatile("fence.proxy.async.shared::cta;" ::: "memory");
        const uint32_t ps = smem_u32(pat);
        for (int c = blockIdx.x; c < nchunks; c += NBLK) {
            asm volatile(
                "cp.async.bulk.global.shared::cta.bulk_group [%0], [%1], %2;"
                :: "l"(out + (size_t)c * CHUNK_F), "r"(ps), "r"(CHUNK_F * 4)
                : "memory");
        }
        asm volatile("cp.async.bulk.commit_group;" ::: "memory");
    }
    // scalar fill of the tail region beyond the last full chunk
    if (blockIdx.x == 0) {
        for (int i = nchunks * CHUNK_F + threadIdx.x; i < E; i += BS)
            out[i] = NEG_MIN;
    }

    // ---- Phase 3: drain queue (parallel mask filter + global push) ----
    const int n = min(q_cnt, QCAP);
    for (int j = threadIdx.x; j < n; j += BS) {
        const int idx = q_ix[j];
        if (cmask[idx]) {
            const int gph = is64 ? (int)((const long long*)b32)[idx] : b32[idx];
            const int p   = atomicAdd(&g_cand_cnt[gph], 1);
            if (p < CAP2) {
                g_cand_fl[gph * CAP2 + p] = flipf(q_sc[j]);
                g_cand_ix[gph * CAP2 + p] = idx;
            }
        }
    }
    __syncthreads();

    // ---- All async fill stores must complete before kernel exit ----
    if (threadIdx.x == 0)
        asm volatile("cp.async.bulk.wait_group 0;" ::: "memory");
}

// ---------------------------------------------------------------------------
// K2: per-graph exact top-K from the candidate list via byte-radix select in
// smem (stable tie-break: score desc, index asc); segmented log-denominator;
// kept writes. Exact gmem radix fallback when the list is unusable.
// ---------------------------------------------------------------------------
__global__ void __launch_bounds__(BS) rank_kernel(
    const float* __restrict__ logits,
    const float* __restrict__ scores,
    const float* __restrict__ stop,
    const int*   __restrict__ cmask,
    const int*   __restrict__ b32,
    float* __restrict__ out,
    int E)
{
    __shared__ unsigned buf_fl[CAP];
    __shared__ int      buf_ix[CAP];
    __shared__ unsigned tb_fl[CAP2];
    __shared__ int      tb_ix[CAP2];
    __shared__ int      s_kidx[TOPK];
    __shared__ float    s_lv[TOPK];
    __shared__ float    s_ld;
    __shared__ int      seg[2];
    __shared__ int      hist[2048];
    __shared__ int      s_found, s_bin, s_above, s_minix, s_kcnt;
    __shared__ unsigned s_Tf;
    __shared__ int      s_Tix;

    const int g   = blockIdx.x;
    const int tid = threadIdx.x;
    const int cnt = g_cand_cnt[g];

    int kc;
    if (cnt >= TOPK && cnt <= CAP2) {
        // ---- Fast path: byte-radix select over the smem candidate list ----
        for (int j = tid; j < cnt; j += BS) {
            buf_fl[j] = g_cand_fl[g * CAP2 + j];
            buf_ix[j] = g_cand_ix[g * CAP2 + j];
        }
        __syncthreads();

        unsigned prefix = 0, pmask = 0;
        int above = 0;
        for (int lvl = 0; lvl < 4; ++lvl) {
            const int shift = 24 - 8 * lvl;
            if (tid < 256) hist[tid] = 0;
            __syncthreads();
            for (int j = tid; j < cnt; j += BS) {
                const unsigned fl = buf_fl[j];
                if ((fl & pmask) == prefix)
                    atomicAdd(&hist[(fl >> shift) & 0xFF], 1);
            }
            __syncthreads();

            if (tid < 32) {
                const int lane = tid;
                const int Kp   = TOPK - above;
                int cum = 0;
                for (int base = 255; base >= 0; base -= 32) {
                    int bin = base - lane;
                    int c   = hist[bin];
                    int incl = c;
                    #pragma unroll
                    for (int off = 1; off < 32; off <<= 1) {
                        int v = __shfl_up_sync(0xffffffffu, incl, off);
                        if (lane >= off) incl += v;
                    }
                    unsigned bal = __ballot_sync(0xffffffffu, cum + incl >= Kp);
                    if (bal) {
                        int first = __ffs(bal) - 1;
                        if (lane == first) { s_bin = bin; s_above = cum + incl - c; }
                        break;
                    }
                    cum += __shfl_sync(0xffffffffu, incl, 31);
                }
            }
            __syncthreads();

            const int b = s_bin;
            const int n = hist[b];
            above  += s_above;
            prefix |= ((unsigned)b) << shift;
            pmask  |= 0xFFu << shift;
            __syncthreads();                    // hist reads done

            if (n <= 64 || lvl == 3) {
                if (tid == 0) s_kcnt = 0;
                __syncthreads();
                for (int j = tid; j < cnt; j += BS) {
                    const unsigned fl = buf_fl[j];
                    if ((fl & pmask) == prefix) {
                        int p = atomicAdd(&s_kcnt, 1);
                        tb_fl[p] = fl; tb_ix[p] = buf_ix[j];
                    }
                }
                __syncthreads();
                const int nn = s_kcnt;
                const int r  = TOPK - 1 - above;
                for (int j = tid; j < nn; j += BS) {
                    const unsigned fj = tb_fl[j];
                    const int      ij = tb_ix[j];
                    int rk = 0;
                    for (int l = 0; l < nn; ++l) {
                        const unsigned fl2 = tb_fl[l];
                        rk += (fl2 > fj) || (fl2 == fj && tb_ix[l] < ij);
                    }
                    if (rk == r) { s_Tf = fj; s_Tix = ij; }
                }
                __syncthreads();
                break;
            }
        }

        const unsigned Tf = s_Tf; const int Tix = s_Tix;
        if (tid == 0) s_kcnt = 0;
        __syncthreads();
        for (int j = tid; j < cnt; j += BS) {
            const unsigned fl = buf_fl[j];
            if (fl > Tf || (fl == Tf && buf_ix[j] <= Tix)) {
                int p = atomicAdd(&s_kcnt, 1);
                s_kidx[p] = buf_ix[j];
            }
        }
        kc = TOPK;
        __syncthreads();
    } else {
        // ---- Fallback: segment bounds + exact 3-level radix over gmem ----
        if (tid < 2) {
            const int target = g + tid;
            int lo = 0;
            if (target == NGRAPH) lo = E;
            else if (target > 0) {
                const bool is64 = (b32[(E - 2) | 1] == 0);
                int hi = E;
                if (is64) {
                    const long long* b = (const long long*)b32;
                    const long long key = (long long)target;
                    while (lo < hi) { int mid = (lo + hi) >> 1; if (b[mid] < key) lo = mid + 1; else hi = mid; }
                } else {
                    while (lo < hi) { int mid = (lo + hi) >> 1; if (b32[mid] < target) lo = mid + 1; else hi = mid; }
                }
            }
            seg[tid] = lo;
        }
        __syncthreads();
        const int s0 = seg[0], s1 = seg[1];

        unsigned prefix = 0, pmask = 0;
        int  above = 0;
        bool keepall = false, have_thr = false;

        for (int lvl = 0; lvl < 3; ++lvl) {
            const int      shift = (lvl == 0) ? 21 : (lvl == 1) ? 10 : 0;
            const unsigned mw    = (lvl == 2) ? 0x3FFu : 0x7FFu;

            for (int j = tid; j < 2048; j += BS) hist[j] = 0;
            if (tid == 0) s_found = 0;
            __syncthreads();

            for (int i = s0 + tid; i < s1; i += BS) {
                if (cmask[i] != 0) {
                    unsigned fl = flipf(scores[i]);
                    if ((fl & pmask) == prefix)
                        atomicAdd(&hist[(fl >> shift) & mw], 1);
                }
            }
            __syncthreads();

            if (tid < 32) {
                const int lane = tid;
                const int Kp   = TOPK - above;
                int cum = 0;
                for (int base = (int)mw; base >= 0; base -= 32) {
                    int bin = base - lane;
                    int c   = (bin >= 0) ? hist[bin] : 0;
                    int incl = c;
                    #pragma unroll
                    for (int off = 1; off < 32; off <<= 1) {
                        int v = __shfl_up_sync(0xffffffffu, incl, off);
                        if (lane >= off) incl += v;
                    }
                    unsigned bal = __ballot_sync(0xffffffffu, cum + incl >= Kp);
                    if (bal) {
                        int first = __ffs(bal) - 1;
                        if (lane == first) { s_bin = bin; s_above = cum + incl - c; s_found = 1; }
                        break;
                    }
                    cum += __shfl_sync(0xffffffffu, incl, 31);
                }
            }
            __syncthreads();

            if (!s_found) { keepall = true; break; }

            const int b = s_bin;
            above  += s_above;
            const int n = hist[b];
            prefix |= ((unsigned)b) << shift;
            pmask  |= mw << shift;
            __syncthreads();

            if (n <= CAP) {
                if (tid == 0) s_kcnt = 0;
                __syncthreads();
                for (int i = s0 + tid; i < s1; i += BS) {
                    if (cmask[i] != 0) {
                        unsigned fl = flipf(scores[i]);
                        if ((fl & pmask) == prefix) {
                            int p = atomicAdd(&s_kcnt, 1);
                            buf_fl[p] = fl; buf_ix[p] = i;
                        }
                    }
                }
                __syncthreads();
                const int nn = s_kcnt;
                const int r  = TOPK - 1 - above;
                for (int j = tid; j < nn; j += BS) {
                    unsigned fj = buf_fl[j]; int ij = buf_ix[j];
                    int rk = 0;
                    for (int l = 0; l < nn; ++l) {
                        unsigned fl2 = buf_fl[l];
                        rk += (fl2 > fj) || (fl2 == fj && buf_ix[l] < ij);
                    }
                    if (rk == r) { s_Tf = fj; s_Tix = ij; }
                }
                have_thr = true;
                __syncthreads();
                break;
            }
        }

        unsigned Tf; int Tix;
        if (keepall)       { Tf = 0u;   Tix = 0x7FFFFFFF; }
        else if (have_thr) { Tf = s_Tf; Tix = s_Tix; }
        else {
            const int m = TOPK - above;
            int last = -1;
            for (int t = 0; t < m; ++t) {
                if (tid == 0) s_minix = 0x7FFFFFFF;
                __syncthreads();
                for (int i = s0 + tid; i < s1; i += BS) {
                    if (cmask[i] != 0 && i > last) {
                        if (flipf(scores[i]) == prefix) atomicMin(&s_minix, i);
                    }
                }
                __syncthreads();
                last = s_minix;
                __syncthreads();
            }
            Tf = prefix; Tix = last;
        }

        if (tid == 0) s_kcnt = 0;
        __syncthreads();
        for (int i = s0 + tid; i < s1; i += BS) {
            if (cmask[i] != 0) {
                unsigned fl = flipf(scores[i]);
                if (fl > Tf || (fl == Tf && i <= Tix)) {
                    int p = atomicAdd(&s_kcnt, 1);
                    if (p < TOPK) s_kidx[p] = i;
                }
            }
        }
        __syncthreads();
        kc = min(s_kcnt, TOPK);
    }

    // ---- Segmented log-denominator over the <=32 kept logits + stop ----
    if (tid < kc) s_lv[tid] = logits[s_kidx[tid]];   // TEMP == 1.0
    __syncthreads();

    if (tid < 32) {
        float v = (tid < kc) ? s_lv[tid] : -INFINITY;
        float mx = v;
        #pragma unroll
        for (int off = 16; off; off >>= 1) mx = fmaxf(mx, __shfl_xor_sync(0xffffffffu, mx, off));
        float e = (tid < kc) ? expf(v - mx) : 0.0f;
        #pragma unroll
        for (int off = 16; off; off >>= 1) e += __shfl_xor_sync(0xffffffffu, e, off);
        if (tid == 0) {
            float st = stop[g];
            float ld;
            if (kc == 0) ld = st;
            else {
                float lse = logf(e) + mx;
                float a = fmaxf(lse, st), b2 = fminf(lse, st);
                ld = a + log1pf(expf(b2 - a));
            }
            s_ld = ld;
        }
    }
    __syncthreads();

    if (tid < kc) out[s_kidx[tid]] = s_lv[tid] - s_ld;

    // Reset this graph's counter for the next (graph-replayed) run.
    if (tid == 0) g_cand_cnt[g] = 0;
}

extern "C" void kernel_launch(void* const* d_in, const int* in_sizes, int n_in,
                              void* d_out, int out_size) {
    const float* logits = (const float*)d_in[0];
    const float* scores = (const float*)d_in[1];
    const float* stop   = (const float*)d_in[2];
    const int*   batch  = (const int*)d_in[3];
    const int*   cmask  = (const int*)d_in[4];
    float* out = (float*)d_out;
    const int E = in_sizes[0];

    scan_kernel<<<NBLK, BS>>>(scores, cmask, batch, out, E);
    rank_kernel<<<NGRAPH, BS>>>(logits, scores, stop, cmask, batch, out, E);
}

// round 13
// speedup vs baseline: 1.0857x; 1.0644x over previous
#include <cuda_runtime.h>
#include <math.h>

#define NGRAPH 1024
#define TOPK 32
#define BS 256
#define NBLK 2048
#define FILLB 942                            // fill blocks (~46% = write share)
#define QCAP 1024                            // per-block smem hit queue
#define CAP2 512                             // per-graph global candidate cap
#define CAP 2048                             // fallback smem cap
#define NEG_MIN (-3.4028234663852886e38f)    // np.finfo(float32).min == -FLT_MAX
#define THR 2.0f                             // prior threshold ~2 sigma

__device__ unsigned g_cand_fl[NGRAPH * CAP2];
__device__ int      g_cand_ix[NGRAPH * CAP2];
__device__ int      g_cand_cnt[NGRAPH];      // zero-init; rank_kernel re-zeros

// Order-preserving float->uint flip: larger float -> larger unsigned.
__device__ __forceinline__ unsigned flipf(float s) {
    unsigned u = __float_as_uint(s);
    return (u & 0x80000000u) ? ~u : (u | 0x80000000u);
}

__device__ __forceinline__ void push_direct(
    const int* __restrict__ cmask, const int* __restrict__ b32,
    bool is64, int idx, float s)
{
    if (cmask[idx]) {
        const int gph = is64 ? (int)((const long long*)b32)[idx] : b32[idx];
        const int p   = atomicAdd(&g_cand_cnt[gph], 1);
        if (p < CAP2) {
            g_cand_fl[gph * CAP2 + p] = flipf(s);
            g_cand_ix[gph * CAP2 + p] = idx;
        }
    }
}

// ---------------------------------------------------------------------------
// K1: role-split + smem queue. Fill blocks run a PURE STG.128 stream (no
// latency exposure). Scan blocks run a PURE LDG.128 stream with threshold
// hits pushed to a per-block smem queue (no gmem dependency in the loop); a
// drain phase then filters via cmask (parallel, high MLP) and pushes
// survivors to the owning graph's global candidate list.
// ---------------------------------------------------------------------------
__global__ void __launch_bounds__(BS) scan_kernel(
    const float* __restrict__ scores,
    const int*   __restrict__ cmask,        // bool delivered as int32
    const int*   __restrict__ b32,          // edge_batch (int32 or int64 words)
    float* __restrict__ out,
    int E)
{
    const int nv = E >> 2;

    if (blockIdx.x < FILLB) {
        // ---- Pure fill stream ----
        const float4 v4 = make_float4(NEG_MIN, NEG_MIN, NEG_MIN, NEG_MIN);
        float4* o4 = (float4*)out;
        const int gid = blockIdx.x * BS + threadIdx.x;
        const int gsz = FILLB * BS;
        #pragma unroll 8
        for (int v = gid; v < nv; v += gsz) __stcs(o4 + v, v4);
        if (blockIdx.x == 0) {               // scalar tail (E % 4)
            for (int i = (nv << 2) + threadIdx.x; i < E; i += BS) out[i] = NEG_MIN;
        }
        return;
    }

    // ---- Scan role ----
    __shared__ int   q_cnt;
    __shared__ float q_sc[QCAP];
    __shared__ int   q_ix[QCAP];

    const bool is64 = (b32[(E - 2) | 1] == 0);   // dtype sniff (L1-broadcast)
    const float4* sc4 = (const float4*)scores;
    const int sb  = blockIdx.x - FILLB;
    const int nsb = NBLK - FILLB;
    const int gid = sb * BS + threadIdx.x;
    const int gsz = nsb * BS;

    if (threadIdx.x == 0) q_cnt = 0;
    __syncthreads();

    // Pure read loop + smem-queue push.
    #pragma unroll 8
    for (int v = gid; v < nv; v += gsz) {
        const float4 sc = __ldcs(sc4 + v);
        const float  mx = fmaxf(fmaxf(sc.x, sc.y), fmaxf(sc.z, sc.w));
        if (mx > THR) {
            const int i = v << 2;
            #pragma unroll
            for (int w = 0; w < 4; ++w) {
                const float s = (w == 0) ? sc.x : (w == 1) ? sc.y : (w == 2) ? sc.z : sc.w;
                if (s > THR) {
                    const int p = atomicAdd(&q_cnt, 1);
                    if (p < QCAP) { q_sc[p] = s; q_ix[p] = i + w; }
                    else          push_direct(cmask, b32, is64, i + w, s);  // overflow (never in practice)
                }
            }
        }
    }
    // scalar score tail (E % 4)
    if (sb == 0) {
        for (int i = (nv << 2) + threadIdx.x; i < E; i += BS) {
            const float s = scores[i];
            if (s > THR) {
                const int p = atomicAdd(&q_cnt, 1);
                if (p < QCAP) { q_sc[p] = s; q_ix[p] = i; }
                else          push_direct(cmask, b32, is64, i, s);
            }
        }
    }
    __syncthreads();

    // Drain: parallel mask filter + global push.
    const int n = min(q_cnt, QCAP);
    for (int j = threadIdx.x; j < n; j += BS) {
        const int idx = q_ix[j];
        if (cmask[idx]) {
            const int gph = is64 ? (int)((const long long*)b32)[idx] : b32[idx];
            const int p   = atomicAdd(&g_cand_cnt[gph], 1);
            if (p < CAP2) {
                g_cand_fl[gph * CAP2 + p] = flipf(q_sc[j]);
                g_cand_ix[gph * CAP2 + p] = idx;
            }
        }
    }
}

// ---------------------------------------------------------------------------
// K2: per-graph exact top-K from the candidate list via byte-radix select in
// smem (stable tie-break: score desc, index asc); segmented log-denominator;
// kept writes. Exact gmem radix fallback when the list is unusable.
// ---------------------------------------------------------------------------
__global__ void __launch_bounds__(BS) rank_kernel(
    const float* __restrict__ logits,
    const float* __restrict__ scores,
    const float* __restrict__ stop,
    const int*   __restrict__ cmask,
    const int*   __restrict__ b32,
    float* __restrict__ out,
    int E)
{
    __shared__ unsigned buf_fl[CAP];
    __shared__ int      buf_ix[CAP];
    __shared__ unsigned tb_fl[CAP2];
    __shared__ int      tb_ix[CAP2];
    __shared__ int      s_kidx[TOPK];
    __shared__ float    s_lv[TOPK];
    __shared__ float    s_ld;
    __shared__ int      seg[2];
    __shared__ int      hist[2048];
    __shared__ int      s_found, s_bin, s_above, s_minix, s_kcnt;
    __shared__ unsigned s_Tf;
    __shared__ int      s_Tix;

    const int g   = blockIdx.x;
    const int tid = threadIdx.x;
    const int cnt = g_cand_cnt[g];

    int kc;
    if (cnt >= TOPK && cnt <= CAP2) {
        // ---- Fast path: byte-radix select over the smem candidate list ----
        for (int j = tid; j < cnt; j += BS) {
            buf_fl[j] = g_cand_fl[g * CAP2 + j];
            buf_ix[j] = g_cand_ix[g * CAP2 + j];
        }
        __syncthreads();

        unsigned prefix = 0, pmask = 0;
        int above = 0;
        for (int lvl = 0; lvl < 4; ++lvl) {
            const int shift = 24 - 8 * lvl;
            if (tid < 256) hist[tid] = 0;
            __syncthreads();
            for (int j = tid; j < cnt; j += BS) {
                const unsigned fl = buf_fl[j];
                if ((fl & pmask) == prefix)
                    atomicAdd(&hist[(fl >> shift) & 0xFF], 1);
            }
            __syncthreads();

            if (tid < 32) {
                const int lane = tid;
                const int Kp   = TOPK - above;
                int cum = 0;
                for (int base = 255; base >= 0; base -= 32) {
                    int bin = base - lane;
                    int c   = hist[bin];
                    int incl = c;
                    #pragma unroll
                    for (int off = 1; off < 32; off <<= 1) {
                        int v = __shfl_up_sync(0xffffffffu, incl, off);
                        if (lane >= off) incl += v;
                    }
                    unsigned bal = __ballot_sync(0xffffffffu, cum + incl >= Kp);
                    if (bal) {
                        int first = __ffs(bal) - 1;
                        if (lane == first) { s_bin = bin; s_above = cum + incl - c; }
                        break;
                    }
                    cum += __shfl_sync(0xffffffffu, incl, 31);
                }
            }
            __syncthreads();

            const int b = s_bin;
            const int n = hist[b];
            above  += s_above;
            prefix |= ((unsigned)b) << shift;
            pmask  |= 0xFFu << shift;
            __syncthreads();                    // hist reads done

            if (n <= 64 || lvl == 3) {
                if (tid == 0) s_kcnt = 0;
                __syncthreads();
                for (int j = tid; j < cnt; j += BS) {
                    const unsigned fl = buf_fl[j];
                    if ((fl & pmask) == prefix) {
                        int p = atomicAdd(&s_kcnt, 1);
                        tb_fl[p] = fl; tb_ix[p] = buf_ix[j];
                    }
                }
                __syncthreads();
                const int nn = s_kcnt;
                const int r  = TOPK - 1 - above;
                for (int j = tid; j < nn; j += BS) {
                    const unsigned fj = tb_fl[j];
                    const int      ij = tb_ix[j];
                    int rk = 0;
                    for (int l = 0; l < nn; ++l) {
                        const unsigned fl2 = tb_fl[l];
                        rk += (fl2 > fj) || (fl2 == fj && tb_ix[l] < ij);
                    }
                    if (rk == r) { s_Tf = fj; s_Tix = ij; }
                }
                __syncthreads();
                break;
            }
        }

        const unsigned Tf = s_Tf; const int Tix = s_Tix;
        if (tid == 0) s_kcnt = 0;
        __syncthreads();
        for (int j = tid; j < cnt; j += BS) {
            const unsigned fl = buf_fl[j];
            if (fl > Tf || (fl == Tf && buf_ix[j] <= Tix)) {
                int p = atomicAdd(&s_kcnt, 1);
                s_kidx[p] = buf_ix[j];
            }
        }
        kc = TOPK;
        __syncthreads();
    } else {
        // ---- Fallback: segment bounds + exact 3-level radix over gmem ----
        if (tid < 2) {
            const int target = g + tid;
            int lo = 0;
            if (target == NGRAPH) lo = E;
            else if (target > 0) {
                const bool is64 = (b32[(E - 2) | 1] == 0);
                int hi = E;
                if (is64) {
                    const long long* b = (const long long*)b32;
                    const long long key = (long long)target;
                    while (lo < hi) { int mid = (lo + hi) >> 1; if (b[mid] < key) lo = mid + 1; else hi = mid; }
                } else {
                    while (lo < hi) { int mid = (lo + hi) >> 1; if (b32[mid] < target) lo = mid + 1; else hi = mid; }
                }
            }
            seg[tid] = lo;
        }
        __syncthreads();
        const int s0 = seg[0], s1 = seg[1];

        unsigned prefix = 0, pmask = 0;
        int  above = 0;
        bool keepall = false, have_thr = false;

        for (int lvl = 0; lvl < 3; ++lvl) {
            const int      shift = (lvl == 0) ? 21 : (lvl == 1) ? 10 : 0;
            const unsigned mw    = (lvl == 2) ? 0x3FFu : 0x7FFu;

            for (int j = tid; j < 2048; j += BS) hist[j] = 0;
            if (tid == 0) s_found = 0;
            __syncthreads();

            for (int i = s0 + tid; i < s1; i += BS) {
                if (cmask[i] != 0) {
                    unsigned fl = flipf(scores[i]);
                    if ((fl & pmask) == prefix)
                        atomicAdd(&hist[(fl >> shift) & mw], 1);
                }
            }
            __syncthreads();

            if (tid < 32) {
                const int lane = tid;
                const int Kp   = TOPK - above;
                int cum = 0;
                for (int base = (int)mw; base >= 0; base -= 32) {
                    int bin = base - lane;
                    int c   = (bin >= 0) ? hist[bin] : 0;
                    int incl = c;
                    #pragma unroll
                    for (int off = 1; off < 32; off <<= 1) {
                        int v = __shfl_up_sync(0xffffffffu, incl, off);
                        if (lane >= off) incl += v;
                    }
                    unsigned bal = __ballot_sync(0xffffffffu, cum + incl >= Kp);
                    if (bal) {
                        int first = __ffs(bal) - 1;
                        if (lane == first) { s_bin = bin; s_above = cum + incl - c; s_found = 1; }
                        break;
                    }
                    cum += __shfl_sync(0xffffffffu, incl, 31);
                }
            }
            __syncthreads();

            if (!s_found) { keepall = true; break; }

            const int b = s_bin;
            above  += s_above;
            const int n = hist[b];
            prefix |= ((unsigned)b) << shift;
            pmask  |= mw << shift;
            __syncthreads();

            if (n <= CAP) {
                if (tid == 0) s_kcnt = 0;
                __syncthreads();
                for (int i = s0 + tid; i < s1; i += BS) {
                    if (cmask[i] != 0) {
                        unsigned fl = flipf(scores[i]);
                        if ((fl & pmask) == prefix) {
                            int p = atomicAdd(&s_kcnt, 1);
                            buf_fl[p] = fl; buf_ix[p] = i;
                        }
                    }
                }
                __syncthreads();
                const int nn = s_kcnt;
                const int r  = TOPK - 1 - above;
                for (int j = tid; j < nn; j += BS) {
                    unsigned fj = buf_fl[j]; int ij = buf_ix[j];
                    int rk = 0;
                    for (int l = 0; l < nn; ++l) {
                        unsigned fl2 = buf_fl[l];
                        rk += (fl2 > fj) || (fl2 == fj && buf_ix[l] < ij);
                    }
                    if (rk == r) { s_Tf = fj; s_Tix = ij; }
                }
                have_thr = true;
                __syncthreads();
                break;
            }
        }

        unsigned Tf; int Tix;
        if (keepall)       { Tf = 0u;   Tix = 0x7FFFFFFF; }
        else if (have_thr) { Tf = s_Tf; Tix = s_Tix; }
        else {
            const int m = TOPK - above;
            int last = -1;
            for (int t = 0; t < m; ++t) {
                if (tid == 0) s_minix = 0x7FFFFFFF;
                __syncthreads();
                for (int i = s0 + tid; i < s1; i += BS) {
                    if (cmask[i] != 0 && i > last) {
                        if (flipf(scores[i]) == prefix) atomicMin(&s_minix, i);
                    }
                }
                __syncthreads();
                last = s_minix;
                __syncthreads();
            }
            Tf = prefix; Tix = last;
        }

        if (tid == 0) s_kcnt = 0;
        __syncthreads();
        for (int i = s0 + tid; i < s1; i += BS) {
            if (cmask[i] != 0) {
                unsigned fl = flipf(scores[i]);
                if (fl > Tf || (fl == Tf && i <= Tix)) {
                    int p = atomicAdd(&s_kcnt, 1);
                    if (p < TOPK) s_kidx[p] = i;
                }
            }
        }
        __syncthreads();
        kc = min(s_kcnt, TOPK);
    }

    // ---- Segmented log-denominator over the <=32 kept logits + stop ----
    if (tid < kc) s_lv[tid] = logits[s_kidx[tid]];   // TEMP == 1.0
    __syncthreads();

    if (tid < 32) {
        float v = (tid < kc) ? s_lv[tid] : -INFINITY;
        float mx = v;
        #pragma unroll
        for (int off = 16; off; off >>= 1) mx = fmaxf(mx, __shfl_xor_sync(0xffffffffu, mx, off));
        float e = (tid < kc) ? expf(v - mx) : 0.0f;
        #pragma unroll
        for (int off = 16; off; off >>= 1) e += __shfl_xor_sync(0xffffffffu, e, off);
        if (tid == 0) {
            float st = stop[g];
            float ld;
            if (kc == 0) ld = st;
            else {
                float lse = logf(e) + mx;
                float a = fmaxf(lse, st), b2 = fminf(lse, st);
                ld = a + log1pf(expf(b2 - a));
            }
            s_ld = ld;
        }
    }
    __syncthreads();

    if (tid < kc) out[s_kidx[tid]] = s_lv[tid] - s_ld;

    // Reset this graph's counter for the next (graph-replayed) run.
    if (tid == 0) g_cand_cnt[g] = 0;
}

extern "C" void kernel_launch(void* const* d_in, const int* in_sizes, int n_in,
                              void* d_out, int out_size) {
    const float* logits = (const float*)d_in[0];
    const float* scores = (const float*)d_in[1];
    const float* stop   = (const float*)d_in[2];
    const int*   batch  = (const int*)d_in[3];
    const int*   cmask  = (const int*)d_in[4];
    float* out = (float*)d_out;
    const int E = in_sizes[0];

    scan_kernel<<<NBLK, BS>>>(scores, cmask, batch, out, E);
    rank_kernel<<<NGRAPH, BS>>>(logits, scores, stop, cmask, batch, out, E);
}

// round 14
// speedup vs baseline: 1.0903x; 1.0043x over previous
#include <cuda_runtime.h>
#include <math.h>
#include <cstdint>

#define NGRAPH 1024
#define TOPK 32
#define BS 256
#define NBLK 2048
#define VPT 8                                // front-batched vectors per thread
#define QCAP 1024                            // per-block smem hit queue
#define CAP2 512                             // per-graph global candidate cap
#define CAP 2048                             // fallback smem cap
#define CHUNK_F 4096                         // 16 KB fill chunk (floats)
#define NEG_MIN (-3.4028234663852886e38f)    // np.finfo(float32).min == -FLT_MAX
#define THR 2.0f                             // prior threshold ~2 sigma

__device__ unsigned g_cand_fl[NGRAPH * CAP2];
__device__ int      g_cand_ix[NGRAPH * CAP2];
__device__ int      g_cand_cnt[NGRAPH];      // zero-init; rank_kernel re-zeros

// Order-preserving float->uint flip: larger float -> larger unsigned.
__device__ __forceinline__ unsigned flipf(float s) {
    unsigned u = __float_as_uint(s);
    return (u & 0x80000000u) ? ~u : (u | 0x80000000u);
}

__device__ __forceinline__ uint32_t smem_u32(const void* p) {
    uint32_t a;
    asm("{ .reg .u64 t; cvta.to.shared.u64 t, %1; cvt.u32.u64 %0, t; }"
        : "=r"(a) : "l"(p));
    return a;
}

__device__ __forceinline__ void push_direct(
    const int* __restrict__ cmask, const int* __restrict__ b32,
    bool is64, int idx, float s)
{
    if (cmask[idx]) {
        const int gph = is64 ? (int)((const long long*)b32)[idx] : b32[idx];
        const int p   = atomicAdd(&g_cand_cnt[gph], 1);
        if (p < CAP2) {
            g_cand_fl[gph * CAP2 + p] = flipf(s);
            g_cand_ix[gph * CAP2 + p] = idx;
        }
    }
}

// ---------------------------------------------------------------------------
// K1: TMA fill + latency-immune read scan.
//  - 64MB NEG_MIN fill leaves the warp stream entirely: per block, thread 0
//    issues its cp.async.bulk 16KB chunks (the LSU instruction floor drops
//    from 8M to 4M memory instructions).
//  - Reads are front-batched VPT=8 deep into registers, so the elevated
//    queue latency from concurrent TMA writes is overlapped 8-deep.
//  - Threshold hits go to a per-block smem queue; the drain phase filters
//    via cmask (parallel loads) and pushes to per-graph global lists.
// ---------------------------------------------------------------------------
__global__ void __launch_bounds__(BS) scan_kernel(
    const float* __restrict__ scores,
    const int*   __restrict__ cmask,        // bool delivered as int32
    const int*   __restrict__ b32,          // edge_batch (int32 or int64 words)
    float* __restrict__ out,
    int E)
{
    __shared__ int   q_cnt;
    __shared__ float q_sc[QCAP];
    __shared__ int   q_ix[QCAP];
    __shared__ __align__(16) float pat[CHUNK_F];   // 16 KB fill pattern

    const int  nv   = E >> 2;
    const int  gsz  = NBLK * BS;
    const int  v0   = blockIdx.x * BS + threadIdx.x;
    const bool is64 = (b32[(E - 2) | 1] == 0);   // dtype sniff (L1-broadcast)

    for (int i = threadIdx.x; i < CHUNK_F; i += BS) pat[i] = NEG_MIN;
    if (threadIdx.x == 0) q_cnt = 0;
    __syncthreads();

    // ---- Issue async TMA fill chunks for this block ----
    const int nchunks = E / CHUNK_F;
    if (threadIdx.x == 0) {
        asm volatile("fence.proxy.async.shared::cta;" ::: "memory");
        const uint32_t ps = smem_u32(pat);
        for (int c = blockIdx.x; c < nchunks; c += NBLK) {
            asm volatile(
                "cp.async.bulk.global.shared::cta.bulk_group [%0], [%1], %2;"
                :: "l"(out + (size_t)c * CHUNK_F), "r"(ps), "r"(CHUNK_F * 4)
                : "memory");
        }
        asm volatile("cp.async.bulk.commit_group;" ::: "memory");
    }
    if (blockIdx.x == 0) {                   // scalar fill beyond last chunk
        for (int i = nchunks * CHUNK_F + threadIdx.x; i < E; i += BS)
            out[i] = NEG_MIN;
    }

    // ---- Front-batched read phase: 8 independent LDG.128 per thread ----
    const float4* sc4 = (const float4*)scores;
    float4 r[VPT];
    bool   ok[VPT];
    #pragma unroll
    for (int k = 0; k < VPT; ++k) {
        const int v = v0 + k * gsz;
        ok[k] = v < nv;
        if (ok[k]) r[k] = __ldcs(sc4 + v);
    }
    #pragma unroll
    for (int k = 0; k < VPT; ++k) {
        if (!ok[k]) continue;
        const float4 sc = r[k];
        const float  mx = fmaxf(fmaxf(sc.x, sc.y), fmaxf(sc.z, sc.w));
        if (mx > THR) {
            const int i = (v0 + k * gsz) << 2;
            #pragma unroll
            for (int w = 0; w < 4; ++w) {
                const float s = (w == 0) ? sc.x : (w == 1) ? sc.y : (w == 2) ? sc.z : sc.w;
                if (s > THR) {
                    const int p = atomicAdd(&q_cnt, 1);
                    if (p < QCAP) { q_sc[p] = s; q_ix[p] = i + w; }
                    else          push_direct(cmask, b32, is64, i + w, s);
                }
            }
        }
    }
    // safety: any vectors beyond VPT*gsz (other shapes)
    for (int v = v0 + VPT * gsz; v < nv; v += gsz) {
        const float4 sc = __ldcs(sc4 + v);
        const float  mx = fmaxf(fmaxf(sc.x, sc.y), fmaxf(sc.z, sc.w));
        if (mx > THR) {
            const int i = v << 2;
            #pragma unroll
            for (int w = 0; w < 4; ++w) {
                const float s = (w == 0) ? sc.x : (w == 1) ? sc.y : (w == 2) ? sc.z : sc.w;
                if (s > THR) {
                    const int p = atomicAdd(&q_cnt, 1);
                    if (p < QCAP) { q_sc[p] = s; q_ix[p] = i + w; }
                    else          push_direct(cmask, b32, is64, i + w, s);
                }
            }
        }
    }
    // scalar score tail (E % 4)
    if (blockIdx.x == 0) {
        for (int i = (nv << 2) + threadIdx.x; i < E; i += BS) {
            const float s = scores[i];
            if (s > THR) {
                const int p = atomicAdd(&q_cnt, 1);
                if (p < QCAP) { q_sc[p] = s; q_ix[p] = i; }
                else          push_direct(cmask, b32, is64, i, s);
            }
        }
    }
    __syncthreads();

    // ---- Drain: parallel mask filter + global push ----
    const int n = min(q_cnt, QCAP);
    for (int j = threadIdx.x; j < n; j += BS) {
        const int idx = q_ix[j];
        if (cmask[idx]) {
            const int gph = is64 ? (int)((const long long*)b32)[idx] : b32[idx];
            const int p   = atomicAdd(&g_cand_cnt[gph], 1);
            if (p < CAP2) {
                g_cand_fl[gph * CAP2 + p] = flipf(q_sc[j]);
                g_cand_ix[gph * CAP2 + p] = idx;
            }
        }
    }
    __syncthreads();

    // ---- All async fill stores must complete before kernel exit ----
    if (threadIdx.x == 0)
        asm volatile("cp.async.bulk.wait_group 0;" ::: "memory");
}

// ---------------------------------------------------------------------------
// K2: per-graph exact top-K from the candidate list via byte-radix select in
// smem (stable tie-break: score desc, index asc); segmented log-denominator;
// kept writes. Exact gmem radix fallback when the list is unusable.
// ---------------------------------------------------------------------------
__global__ void __launch_bounds__(BS) rank_kernel(
    const float* __restrict__ logits,
    const float* __restrict__ scores,
    const float* __restrict__ stop,
    const int*   __restrict__ cmask,
    const int*   __restrict__ b32,
    float* __restrict__ out,
    int E)
{
    __shared__ unsigned buf_fl[CAP];
    __shared__ int      buf_ix[CAP];
    __shared__ unsigned tb_fl[CAP2];
    __shared__ int      tb_ix[CAP2];
    __shared__ int      s_kidx[TOPK];
    __shared__ float    s_lv[TOPK];
    __shared__ float    s_ld;
    __shared__ int      seg[2];
    __shared__ int      hist[2048];
    __shared__ int      s_found, s_bin, s_above, s_minix, s_kcnt;
    __shared__ unsigned s_Tf;
    __shared__ int      s_Tix;

    const int g   = blockIdx.x;
    const int tid = threadIdx.x;
    const int cnt = g_cand_cnt[g];

    int kc;
    if (cnt >= TOPK && cnt <= CAP2) {
        for (int j = tid; j < cnt; j += BS) {
            buf_fl[j] = g_cand_fl[g * CAP2 + j];
            buf_ix[j] = g_cand_ix[g * CAP2 + j];
        }
        __syncthreads();

        unsigned prefix = 0, pmask = 0;
        int above = 0;
        for (int lvl = 0; lvl < 4; ++lvl) {
            const int shift = 24 - 8 * lvl;
            if (tid < 256) hist[tid] = 0;
            __syncthreads();
            for (int j = tid; j < cnt; j += BS) {
                const unsigned fl = buf_fl[j];
                if ((fl & pmask) == prefix)
                    atomicAdd(&hist[(fl >> shift) & 0xFF], 1);
            }
            __syncthreads();

            if (tid < 32) {
                const int lane = tid;
                const int Kp   = TOPK - above;
                int cum = 0;
                for (int base = 255; base >= 0; base -= 32) {
                    int bin = base - lane;
                    int c   = hist[bin];
                    int incl = c;
                    #pragma unroll
                    for (int off = 1; off < 32; off <<= 1) {
                        int v = __shfl_up_sync(0xffffffffu, incl, off);
                        if (lane >= off) incl += v;
                    }
                    unsigned bal = __ballot_sync(0xffffffffu, cum + incl >= Kp);
                    if (bal) {
                        int first = __ffs(bal) - 1;
                        if (lane == first) { s_bin = bin; s_above = cum + incl - c; }
                        break;
                    }
                    cum += __shfl_sync(0xffffffffu, incl, 31);
                }
            }
            __syncthreads();

            const int b = s_bin;
            const int n = hist[b];
            above  += s_above;
            prefix |= ((unsigned)b) << shift;
            pmask  |= 0xFFu << shift;
            __syncthreads();

            if (n <= 64 || lvl == 3) {
                if (tid == 0) s_kcnt = 0;
                __syncthreads();
                for (int j = tid; j < cnt; j += BS) {
                    const unsigned fl = buf_fl[j];
                    if ((fl & pmask) == prefix) {
                        int p = atomicAdd(&s_kcnt, 1);
                        tb_fl[p] = fl; tb_ix[p] = buf_ix[j];
                    }
                }
                __syncthreads();
                const int nn = s_kcnt;
                const int r  = TOPK - 1 - above;
                for (int j = tid; j < nn; j += BS) {
                    const unsigned fj = tb_fl[j];
                    const int      ij = tb_ix[j];
                    int rk = 0;
                    for (int l = 0; l < nn; ++l) {
                        const unsigned fl2 = tb_fl[l];
                        rk += (fl2 > fj) || (fl2 == fj && tb_ix[l] < ij);
                    }
                    if (rk == r) { s_Tf = fj; s_Tix = ij; }
                }
                __syncthreads();
                break;
            }
        }

        const unsigned Tf = s_Tf; const int Tix = s_Tix;
        if (tid == 0) s_kcnt = 0;
        __syncthreads();
        for (int j = tid; j < cnt; j += BS) {
            const unsigned fl = buf_fl[j];
            if (fl > Tf || (fl == Tf && buf_ix[j] <= Tix)) {
                int p = atomicAdd(&s_kcnt, 1);
                s_kidx[p] = buf_ix[j];
            }
        }
        kc = TOPK;
        __syncthreads();
    } else {
        if (tid < 2) {
            const int target = g + tid;
            int lo = 0;
            if (target == NGRAPH) lo = E;
            else if (target > 0) {
                const bool is64 = (b32[(E - 2) | 1] == 0);
                int hi = E;
                if (is64) {
                    const long long* b = (const long long*)b32;
                    const long long key = (long long)target;
                    while (lo < hi) { int mid = (lo + hi) >> 1; if (b[mid] < key) lo = mid + 1; else hi = mid; }
                } else {
                    while (lo < hi) { int mid = (lo + hi) >> 1; if (b32[mid] < target) lo = mid + 1; else hi = mid; }
                }
            }
            seg[tid] = lo;
        }
        __syncthreads();
        const int s0 = seg[0], s1 = seg[1];

        unsigned prefix = 0, pmask = 0;
        int  above = 0;
        bool keepall = false, have_thr = false;

        for (int lvl = 0; lvl < 3; ++lvl) {
            const int      shift = (lvl == 0) ? 21 : (lvl == 1) ? 10 : 0;
            const unsigned mw    = (lvl == 2) ? 0x3FFu : 0x7FFu;

            for (int j = tid; j < 2048; j += BS) hist[j] = 0;
            if (tid == 0) s_found = 0;
            __syncthreads();

            for (int i = s0 + tid; i < s1; i += BS) {
                if (cmask[i] != 0) {
                    unsigned fl = flipf(scores[i]);
                    if ((fl & pmask) == prefix)
                        atomicAdd(&hist[(fl >> shift) & mw], 1);
                }
            }
            __syncthreads();

            if (tid < 32) {
                const int lane = tid;
                const int Kp   = TOPK - above;
                int cum = 0;
                for (int base = (int)mw; base >= 0; base -= 32) {
                    int bin = base - lane;
                    int c   = (bin >= 0) ? hist[bin] : 0;
                    int incl = c;
                    #pragma unroll
                    for (int off = 1; off < 32; off <<= 1) {
                        int v = __shfl_up_sync(0xffffffffu, incl, off);
                        if (lane >= off) incl += v;
                    }
                    unsigned bal = __ballot_sync(0xffffffffu, cum + incl >= Kp);
                    if (bal) {
                        int first = __ffs(bal) - 1;
                        if (lane == first) { s_bin = bin; s_above = cum + incl - c; s_found = 1; }
                        break;
                    }
                    cum += __shfl_sync(0xffffffffu, incl, 31);
                }
            }
            __syncthreads();

            if (!s_found) { keepall = true; break; }

            const int b = s_bin;
            above  += s_above;
            const int n = hist[b];
            prefix |= ((unsigned)b) << shift;
            pmask  |= mw << shift;
            __syncthreads();

            if (n <= CAP) {
                if (tid == 0) s_kcnt = 0;
                __syncthreads();
                for (int i = s0 + tid; i < s1; i += BS) {
                    if (cmask[i] != 0) {
                        unsigned fl = flipf(scores[i]);
                        if ((fl & pmask) == prefix) {
                            int p = atomicAdd(&s_kcnt, 1);
                            buf_fl[p] = fl; buf_ix[p] = i;
                        }
                    }
                }
                __syncthreads();
                const int nn = s_kcnt;
                const int r  = TOPK - 1 - above;
                for (int j = tid; j < nn; j += BS) {
                    unsigned fj = buf_fl[j]; int ij = buf_ix[j];
                    int rk = 0;
                    for (int l = 0; l < nn; ++l) {
                        unsigned fl2 = buf_fl[l];
                        rk += (fl2 > fj) || (fl2 == fj && buf_ix[l] < ij);
                    }
                    if (rk == r) { s_Tf = fj; s_Tix = ij; }
                }
                have_thr = true;
                __syncthreads();
                break;
            }
        }

        unsigned Tf; int Tix;
        if (keepall)       { Tf = 0u;   Tix = 0x7FFFFFFF; }
        else if (have_thr) { Tf = s_Tf; Tix = s_Tix; }
        else {
            const int m = TOPK - above;
            int last = -1;
            for (int t = 0; t < m; ++t) {
                if (tid == 0) s_minix = 0x7FFFFFFF;
                __syncthreads();
                for (int i = s0 + tid; i < s1; i += BS) {
                    if (cmask[i] != 0 && i > last) {
                        if (flipf(scores[i]) == prefix) atomicMin(&s_minix, i);
                    }
                }
                __syncthreads();
                last = s_minix;
                __syncthreads();
            }
            Tf = prefix; Tix = last;
        }

        if (tid == 0) s_kcnt = 0;
        __syncthreads();
        for (int i = s0 + tid; i < s1; i += BS) {
            if (cmask[i] != 0) {
                unsigned fl = flipf(scores[i]);
                if (fl > Tf || (fl == Tf && i <= Tix)) {
                    int p = atomicAdd(&s_kcnt, 1);
                    if (p < TOPK) s_kidx[p] = i;
                }
            }
        }
        __syncthreads();
        kc = min(s_kcnt, TOPK);
    }

    // ---- Segmented log-denominator over the <=32 kept logits + stop ----
    if (tid < kc) s_lv[tid] = logits[s_kidx[tid]];   // TEMP == 1.0
    __syncthreads();

    if (tid < 32) {
        float v = (tid < kc) ? s_lv[tid] : -INFINITY;
        float mx = v;
        #pragma unroll
        for (int off = 16; off; off >>= 1) mx = fmaxf(mx, __shfl_xor_sync(0xffffffffu, mx, off));
        float e = (tid < kc) ? expf(v - mx) : 0.0f;
        #pragma unroll
        for (int off = 16; off; off >>= 1) e += __shfl_xor_sync(0xffffffffu, e, off);
        if (tid == 0) {
            float st = stop[g];
            float ld;
            if (kc == 0) ld = st;
            else {
                float lse = logf(e) + mx;
                float a = fmaxf(lse, st), b2 = fminf(lse, st);
                ld = a + log1pf(expf(b2 - a));
            }
            s_ld = ld;
        }
    }
    __syncthreads();

    if (tid < kc) out[s_kidx[tid]] = s_lv[tid] - s_ld;

    // Reset this graph's counter for the next (graph-replayed) run.
    if (tid == 0) g_cand_cnt[g] = 0;
}

extern "C" void kernel_launch(void* const* d_in, const int* in_sizes, int n_in,
                              void* d_out, int out_size) {
    const float* logits = (const float*)d_in[0];
    const float* scores = (const float*)d_in[1];
    const float* stop   = (const float*)d_in[2];
    const int*   batch  = (const int*)d_in[3];
    const int*   cmask  = (const int*)d_in[4];
    float* out = (float*)d_out;
    const int E = in_sizes[0];

    scan_kernel<<<NBLK, BS>>>(scores, cmask, batch, out, E);
    rank_kernel<<<NGRAPH, BS>>>(logits, scores, stop, cmask, batch, out, E);
}

// round 15
// speedup vs baseline: 1.1697x; 1.0728x over previous
#include <cuda_runtime.h>
#include <math.h>
#include <cstdint>

#define NGRAPH 1024
#define TOPK 32
#define BS 256
#define NBLK 2048
#define QCAP 1024                            // per-block smem hit queue
#define CAP2 512                             // per-graph global candidate cap
#define CAP 2048                             // fallback smem cap
#define FCHUNK_F 2048                        // 8 KB fill chunk (floats)
#define RCHUNK_F 2048                        // 8 KB read chunk (floats)
#define NEG_MIN (-3.4028234663852886e38f)    // np.finfo(float32).min == -FLT_MAX
#define THR 2.0f                             // prior threshold ~2 sigma

__device__ unsigned g_cand_fl[NGRAPH * CAP2];
__device__ int      g_cand_ix[NGRAPH * CAP2];
__device__ int      g_cand_cnt[NGRAPH];      // zero-init; rank_kernel re-zeros

__device__ __forceinline__ unsigned flipf(float s) {
    unsigned u = __float_as_uint(s);
    return (u & 0x80000000u) ? ~u : (u | 0x80000000u);
}

__device__ __forceinline__ uint32_t smem_u32(const void* p) {
    uint32_t a;
    asm("{ .reg .u64 t; cvta.to.shared.u64 t, %1; cvt.u32.u64 %0, t; }"
        : "=r"(a) : "l"(p));
    return a;
}

__device__ __forceinline__ void mbar_init(uint32_t a, int cnt) {
    asm volatile("mbarrier.init.shared.b64 [%0], %1;" :: "r"(a), "r"(cnt) : "memory");
}
__device__ __forceinline__ void mbar_expect_tx(uint32_t a, int bytes) {
    asm volatile("mbarrier.arrive.expect_tx.shared.b64 _, [%0], %1;"
                 :: "r"(a), "r"(bytes) : "memory");
}
__device__ __forceinline__ void mbar_wait(uint32_t a, int parity) {
    asm volatile(
        "{\n\t.reg .pred P;\n"
        "W%=:\n\t"
        "mbarrier.try_wait.parity.acquire.cta.shared::cta.b64 P, [%0], %1;\n\t"
        "@!P bra W%=;\n\t}"
        :: "r"(a), "r"(parity) : "memory");
}
__device__ __forceinline__ void tma_g2s(uint32_t smem_dst, const void* gsrc,
                                        int bytes, uint32_t mbar) {
    asm volatile(
        "cp.async.bulk.shared::cta.global.mbarrier::complete_tx::bytes "
        "[%0], [%1], %2, [%3];"
        :: "r"(smem_dst), "l"(gsrc), "r"(bytes), "r"(mbar) : "memory");
}
__device__ __forceinline__ void tma_s2g(void* gdst, uint32_t smem_src, int bytes) {
    asm volatile(
        "cp.async.bulk.global.shared::cta.bulk_group [%0], [%1], %2;"
        :: "l"(gdst), "r"(smem_src), "r"(bytes) : "memory");
}

__device__ __forceinline__ void push_direct(
    const int* __restrict__ cmask, const int* __restrict__ b32,
    bool is64, int idx, float s)
{
    if (cmask[idx]) {
        const int gph = is64 ? (int)((const long long*)b32)[idx] : b32[idx];
        const int p   = atomicAdd(&g_cand_cnt[gph], 1);
        if (p < CAP2) {
            g_cand_fl[gph * CAP2 + p] = flipf(s);
            g_cand_ix[gph * CAP2 + p] = idx;
        }
    }
}

// ---------------------------------------------------------------------------
// K1: fully TMA-driven streaming scan.
//  - Fill: NEG_MIN pattern tile -> gmem via cp.async.bulk s2g (engine-driven).
//  - Reads: scores streamed gmem -> smem via cp.async.bulk g2s with a 2-stage
//    mbarrier double buffer; warps scan SMEM (no DRAM latency on warp path).
//  - Threshold hits go to the smem queue; drain filters via cmask and pushes
//    to per-graph global candidate lists.
// ---------------------------------------------------------------------------
__global__ void __launch_bounds__(BS) scan_kernel(
    const float* __restrict__ scores,
    const int*   __restrict__ cmask,        // bool delivered as int32
    const int*   __restrict__ b32,          // edge_batch (int32 or int64 words)
    float* __restrict__ out,
    int E)
{
    __shared__ int   q_cnt;
    __shared__ float q_sc[QCAP];
    __shared__ int   q_ix[QCAP];
    __shared__ __align__(16) float pat[FCHUNK_F];
    __shared__ __align__(16) float rbuf[2][RCHUNK_F];
    __shared__ __align__(8)  unsigned long long mbar_sto[2];

    const bool is64 = (b32[(E - 2) | 1] == 0);   // dtype sniff (L1-broadcast)
    const int  tid  = threadIdx.x;

    for (int i = tid; i < FCHUNK_F; i += BS) pat[i] = NEG_MIN;
    if (tid == 0) {
        q_cnt = 0;
        mbar_init(smem_u32(&mbar_sto[0]), 1);
        mbar_init(smem_u32(&mbar_sto[1]), 1);
    }
    __syncthreads();

    const uint32_t mb0 = smem_u32(&mbar_sto[0]);
    const uint32_t mb1 = smem_u32(&mbar_sto[1]);
    const uint32_t ps  = smem_u32(pat);
    const uint32_t rb0 = smem_u32(&rbuf[0][0]);
    const uint32_t rb1 = smem_u32(&rbuf[1][0]);

    // ---- Issue async fills + the first read chunk (thread 0) ----
    const int nfc = E / FCHUNK_F;
    const int nrc = E / RCHUNK_F;
    if (tid == 0) {
        asm volatile("fence.proxy.async.shared::cta;" ::: "memory");
        for (int c = blockIdx.x; c < nfc; c += NBLK)
            tma_s2g(out + (size_t)c * FCHUNK_F, ps, FCHUNK_F * 4);
        asm volatile("cp.async.bulk.commit_group;" ::: "memory");
        if (blockIdx.x < nrc) {
            mbar_expect_tx(mb0, RCHUNK_F * 4);
            tma_g2s(rb0, scores + (size_t)blockIdx.x * RCHUNK_F, RCHUNK_F * 4, mb0);
        }
    }
    if (blockIdx.x == 0) {                   // scalar fill beyond last fill chunk
        for (int i = nfc * FCHUNK_F + tid; i < E; i += BS) out[i] = NEG_MIN;
    }

    // ---- Double-buffered smem scan ----
    int ph0 = 0, ph1 = 0;
    for (int i = 0;; ++i) {
        const int c = blockIdx.x + i * NBLK;
        if (c >= nrc) break;
        const int st = i & 1;
        // issue next chunk into the other buffer
        const int cn = c + NBLK;
        if (tid == 0 && cn < nrc) {
            const uint32_t mbn = st ? mb0 : mb1;
            const uint32_t rbn = st ? rb0 : rb1;
            mbar_expect_tx(mbn, RCHUNK_F * 4);
            tma_g2s(rbn, scores + (size_t)cn * RCHUNK_F, RCHUNK_F * 4, mbn);
        }
        // wait current
        if (st == 0) { mbar_wait(mb0, ph0); ph0 ^= 1; }
        else         { mbar_wait(mb1, ph1); ph1 ^= 1; }
        // scan current buffer from smem
        const float4* rb4 = (const float4*)(st ? &rbuf[1][0] : &rbuf[0][0]);
        const int base = c * RCHUNK_F;
        #pragma unroll
        for (int v = 0; v < RCHUNK_F / 4 / BS; ++v) {
            const int j = tid + v * BS;
            const float4 sc = rb4[j];
            const float  mx = fmaxf(fmaxf(sc.x, sc.y), fmaxf(sc.z, sc.w));
            if (mx > THR) {
                const int ib = base + (j << 2);
                #pragma unroll
                for (int w = 0; w < 4; ++w) {
                    const float s = (w == 0) ? sc.x : (w == 1) ? sc.y : (w == 2) ? sc.z : sc.w;
                    if (s > THR) {
                        const int p = atomicAdd(&q_cnt, 1);
                        if (p < QCAP) { q_sc[p] = s; q_ix[p] = ib + w; }
                        else          push_direct(cmask, b32, is64, ib + w, s);
                    }
                }
            }
        }
        __syncthreads();                     // all consumed before buffer reuse
    }

    // scalar score tail beyond the last read chunk
    if (blockIdx.x == 0) {
        for (int i = nrc * RCHUNK_F + tid; i < E; i += BS) {
            const float s = scores[i];
            if (s > THR) {
                const int p = atomicAdd(&q_cnt, 1);
                if (p < QCAP) { q_sc[p] = s; q_ix[p] = i; }
                else          push_direct(cmask, b32, is64, i, s);
            }
        }
    }
    __syncthreads();

    // ---- Drain: parallel mask filter + global push ----
    const int n = min(q_cnt, QCAP);
    for (int j = tid; j < n; j += BS) {
        const int idx = q_ix[j];
        if (cmask[idx]) {
            const int gph = is64 ? (int)((const long long*)b32)[idx] : b32[idx];
            const int p   = atomicAdd(&g_cand_cnt[gph], 1);
            if (p < CAP2) {
                g_cand_fl[gph * CAP2 + p] = flipf(q_sc[j]);
                g_cand_ix[gph * CAP2 + p] = idx;
            }
        }
    }
    __syncthreads();

    if (tid == 0)
        asm volatile("cp.async.bulk.wait_group 0;" ::: "memory");
}

// ---------------------------------------------------------------------------
// K2: per-graph exact top-K via byte-radix select in smem (stable tie-break:
// score desc, index asc); segmented log-denominator; kept writes. Exact gmem
// radix fallback when the candidate list is unusable.
// ---------------------------------------------------------------------------
__global__ void __launch_bounds__(BS) rank_kernel(
    const float* __restrict__ logits,
    const float* __restrict__ scores,
    const float* __restrict__ stop,
    const int*   __restrict__ cmask,
    const int*   __restrict__ b32,
    float* __restrict__ out,
    int E)
{
    __shared__ unsigned buf_fl[CAP];
    __shared__ int      buf_ix[CAP];
    __shared__ unsigned tb_fl[CAP2];
    __shared__ int      tb_ix[CAP2];
    __shared__ int      s_kidx[TOPK];
    __shared__ float    s_lv[TOPK];
    __shared__ float    s_ld;
    __shared__ int      seg[2];
    __shared__ int      hist[2048];
    __shared__ int      s_found, s_bin, s_above, s_minix, s_kcnt;
    __shared__ unsigned s_Tf;
    __shared__ int      s_Tix;

    const int g   = blockIdx.x;
    const int tid = threadIdx.x;
    const int cnt = g_cand_cnt[g];

    int kc;
    if (cnt >= TOPK && cnt <= CAP2) {
        for (int j = tid; j < cnt; j += BS) {
            buf_fl[j] = g_cand_fl[g * CAP2 + j];
            buf_ix[j] = g_cand_ix[g * CAP2 + j];
        }
        __syncthreads();

        unsigned prefix = 0, pmask = 0;
        int above = 0;
        for (int lvl = 0; lvl < 4; ++lvl) {
            const int shift = 24 - 8 * lvl;
            if (tid < 256) hist[tid] = 0;
            __syncthreads();
            for (int j = tid; j < cnt; j += BS) {
                const unsigned fl = buf_fl[j];
                if ((fl & pmask) == prefix)
                    atomicAdd(&hist[(fl >> shift) & 0xFF], 1);
            }
            __syncthreads();

            if (tid < 32) {
                const int lane = tid;
                const int Kp   = TOPK - above;
                int cum = 0;
                for (int base = 255; base >= 0; base -= 32) {
                    int bin = base - lane;
                    int c   = hist[bin];
                    int incl = c;
                    #pragma unroll
                    for (int off = 1; off < 32; off <<= 1) {
                        int v = __shfl_up_sync(0xffffffffu, incl, off);
                        if (lane >= off) incl += v;
                    }
                    unsigned bal = __ballot_sync(0xffffffffu, cum + incl >= Kp);
                    if (bal) {
                        int first = __ffs(bal) - 1;
                        if (lane == first) { s_bin = bin; s_above = cum + incl - c; }
                        break;
                    }
                    cum += __shfl_sync(0xffffffffu, incl, 31);
                }
            }
            __syncthreads();

            const int b = s_bin;
            const int n = hist[b];
            above  += s_above;
            prefix |= ((unsigned)b) << shift;
            pmask  |= 0xFFu << shift;
            __syncthreads();

            if (n <= 64 || lvl == 3) {
                if (tid == 0) s_kcnt = 0;
                __syncthreads();
                for (int j = tid; j < cnt; j += BS) {
                    const unsigned fl = buf_fl[j];
                    if ((fl & pmask) == prefix) {
                        int p = atomicAdd(&s_kcnt, 1);
                        tb_fl[p] = fl; tb_ix[p] = buf_ix[j];
                    }
                }
                __syncthreads();
                const int nn = s_kcnt;
                const int r  = TOPK - 1 - above;
                for (int j = tid; j < nn; j += BS) {
                    const unsigned fj = tb_fl[j];
                    const int      ij = tb_ix[j];
                    int rk = 0;
                    for (int l = 0; l < nn; ++l) {
                        const unsigned fl2 = tb_fl[l];
                        rk += (fl2 > fj) || (fl2 == fj && tb_ix[l] < ij);
                    }
                    if (rk == r) { s_Tf = fj; s_Tix = ij; }
                }
                __syncthreads();
                break;
            }
        }

        const unsigned Tf = s_Tf; const int Tix = s_Tix;
        if (tid == 0) s_kcnt = 0;
        __syncthreads();
        for (int j = tid; j < cnt; j += BS) {
            const unsigned fl = buf_fl[j];
            if (fl > Tf || (fl == Tf && buf_ix[j] <= Tix)) {
                int p = atomicAdd(&s_kcnt, 1);
                s_kidx[p] = buf_ix[j];
            }
        }
        kc = TOPK;
        __syncthreads();
    } else {
        if (tid < 2) {
            const int target = g + tid;
            int lo = 0;
            if (target == NGRAPH) lo = E;
            else if (target > 0) {
                const bool is64 = (b32[(E - 2) | 1] == 0);
                int hi = E;
                if (is64) {
                    const long long* b = (const long long*)b32;
                    const long long key = (long long)target;
                    while (lo < hi) { int mid = (lo + hi) >> 1; if (b[mid] < key) lo = mid + 1; else hi = mid; }
                } else {
                    while (lo < hi) { int mid = (lo + hi) >> 1; if (b32[mid] < target) lo = mid + 1; else hi = mid; }
                }
            }
            seg[tid] = lo;
        }
        __syncthreads();
        const int s0 = seg[0], s1 = seg[1];

        unsigned prefix = 0, pmask = 0;
        int  above = 0;
        bool keepall = false, have_thr = false;

        for (int lvl = 0; lvl < 3; ++lvl) {
            const int      shift = (lvl == 0) ? 21 : (lvl == 1) ? 10 : 0;
            const unsigned mw    = (lvl == 2) ? 0x3FFu : 0x7FFu;

            for (int j = tid; j < 2048; j += BS) hist[j] = 0;
            if (tid == 0) s_found = 0;
            __syncthreads();

            for (int i = s0 + tid; i < s1; i += BS) {
                if (cmask[i] != 0) {
                    unsigned fl = flipf(scores[i]);
                    if ((fl & pmask) == prefix)
                        atomicAdd(&hist[(fl >> shift) & mw], 1);
                }
            }
            __syncthreads();

            if (tid < 32) {
                const int lane = tid;
                const int Kp   = TOPK - above;
                int cum = 0;
                for (int base = (int)mw; base >= 0; base -= 32) {
                    int bin = base - lane;
                    int c   = (bin >= 0) ? hist[bin] : 0;
                    int incl = c;
                    #pragma unroll
                    for (int off = 1; off < 32; off <<= 1) {
                        int v = __shfl_up_sync(0xffffffffu, incl, off);
                        if (lane >= off) incl += v;
                    }
                    unsigned bal = __ballot_sync(0xffffffffu, cum + incl >= Kp);
                    if (bal) {
                        int first = __ffs(bal) - 1;
                        if (lane == first) { s_bin = bin; s_above = cum + incl - c; s_found = 1; }
                        break;
                    }
                    cum += __shfl_sync(0xffffffffu, incl, 31);
                }
            }
            __syncthreads();

            if (!s_found) { keepall = true; break; }

            const int b = s_bin;
            above  += s_above;
            const int n = hist[b];
            prefix |= ((unsigned)b) << shift;
            pmask  |= mw << shift;
            __syncthreads();

            if (n <= CAP) {
                if (tid == 0) s_kcnt = 0;
                __syncthreads();
                for (int i = s0 + tid; i < s1; i += BS) {
                    if (cmask[i] != 0) {
                        unsigned fl = flipf(scores[i]);
                        if ((fl & pmask) == prefix) {
                            int p = atomicAdd(&s_kcnt, 1);
                            buf_fl[p] = fl; buf_ix[p] = i;
                        }
                    }
                }
                __syncthreads();
                const int nn = s_kcnt;
                const int r  = TOPK - 1 - above;
                for (int j = tid; j < nn; j += BS) {
                    unsigned fj = buf_fl[j]; int ij = buf_ix[j];
                    int rk = 0;
                    for (int l = 0; l < nn; ++l) {
                        unsigned fl2 = buf_fl[l];
                        rk += (fl2 > fj) || (fl2 == fj && buf_ix[l] < ij);
                    }
                    if (rk == r) { s_Tf = fj; s_Tix = ij; }
                }
                have_thr = true;
                __syncthreads();
                break;
            }
        }

        unsigned Tf; int Tix;
        if (keepall)       { Tf = 0u;   Tix = 0x7FFFFFFF; }
        else if (have_thr) { Tf = s_Tf; Tix = s_Tix; }
        else {
            const int m = TOPK - above;
            int last = -1;
            for (int t = 0; t < m; ++t) {
                if (tid == 0) s_minix = 0x7FFFFFFF;
                __syncthreads();
                for (int i = s0 + tid; i < s1; i += BS) {
                    if (cmask[i] != 0 && i > last) {
                        if (flipf(scores[i]) == prefix) atomicMin(&s_minix, i);
                    }
                }
                __syncthreads();
                last = s_minix;
                __syncthreads();
            }
            Tf = prefix; Tix = last;
        }

        if (tid == 0) s_kcnt = 0;
        __syncthreads();
        for (int i = s0 + tid; i < s1; i += BS) {
            if (cmask[i] != 0) {
                unsigned fl = flipf(scores[i]);
                if (fl > Tf || (fl == Tf && i <= Tix)) {
                    int p = atomicAdd(&s_kcnt, 1);
                    if (p < TOPK) s_kidx[p] = i;
                }
            }
        }
        __syncthreads();
        kc = min(s_kcnt, TOPK);
    }

    // ---- Segmented log-denominator over the <=32 kept logits + stop ----
    if (tid < kc) s_lv[tid] = logits[s_kidx[tid]];   // TEMP == 1.0
    __syncthreads();

    if (tid < 32) {
        float v = (tid < kc) ? s_lv[tid] : -INFINITY;
        float mx = v;
        #pragma unroll
        for (int off = 16; off; off >>= 1) mx = fmaxf(mx, __shfl_xor_sync(0xffffffffu, mx, off));
        float e = (tid < kc) ? expf(v - mx) : 0.0f;
        #pragma unroll
        for (int off = 16; off; off >>= 1) e += __shfl_xor_sync(0xffffffffu, e, off);
        if (tid == 0) {
            float st = stop[g];
            float ld;
            if (kc == 0) ld = st;
            else {
                float lse = logf(e) + mx;
                float a = fmaxf(lse, st), b2 = fminf(lse, st);
                ld = a + log1pf(expf(b2 - a));
            }
            s_ld = ld;
        }
    }
    __syncthreads();

    if (tid < kc) out[s_kidx[tid]] = s_lv[tid] - s_ld;

    if (tid == 0) g_cand_cnt[g] = 0;
}

extern "C" void kernel_launch(void* const* d_in, const int* in_sizes, int n_in,
                              void* d_out, int out_size) {
    const float* logits = (const float*)d_in[0];
    const float* scores = (const float*)d_in[1];
    const float* stop   = (const float*)d_in[2];
    const int*   batch  = (const int*)d_in[3];
    const int*   cmask  = (const int*)d_in[4];
    float* out = (float*)d_out;
    const int E = in_sizes[0];

    scan_kernel<<<NBLK, BS>>>(scores, cmask, batch, out, E);
    rank_kernel<<<NGRAPH, BS>>>(logits, scores, stop, cmask, batch, out, E);
}

// round 16
// speedup vs baseline: 1.1799x; 1.0087x over previous
#include <cuda_runtime.h>
#include <math.h>
#include <cstdint>

#define NGRAPH 1024
#define TOPK 32
#define BS 256
#define NBLK 2048
#define NSTAGE 4                             // read pipeline depth
#define QCAP 1024                            // per-block smem hit queue
#define CAP2 512                             // per-graph global candidate cap
#define CAP 2048                             // fallback smem cap
#define FCHUNK_F 2048                        // 8 KB fill chunk (floats)
#define RCHUNK_F 2048                        // 8 KB read chunk (floats)
#define NEG_MIN (-3.4028234663852886e38f)    // np.finfo(float32).min == -FLT_MAX
#define THR 2.0f                             // prior threshold ~2 sigma

__device__ unsigned g_cand_fl[NGRAPH * CAP2];
__device__ int      g_cand_ix[NGRAPH * CAP2];
__device__ int      g_cand_cnt[NGRAPH];      // zero-init; rank_kernel re-zeros

__device__ __forceinline__ unsigned flipf(float s) {
    unsigned u = __float_as_uint(s);
    return (u & 0x80000000u) ? ~u : (u | 0x80000000u);
}

__device__ __forceinline__ uint32_t smem_u32(const void* p) {
    uint32_t a;
    asm("{ .reg .u64 t; cvta.to.shared.u64 t, %1; cvt.u32.u64 %0, t; }"
        : "=r"(a) : "l"(p));
    return a;
}

__device__ __forceinline__ void mbar_init(uint32_t a, int cnt) {
    asm volatile("mbarrier.init.shared.b64 [%0], %1;" :: "r"(a), "r"(cnt) : "memory");
}
__device__ __forceinline__ void mbar_expect_tx(uint32_t a, int bytes) {
    asm volatile("mbarrier.arrive.expect_tx.shared.b64 _, [%0], %1;"
                 :: "r"(a), "r"(bytes) : "memory");
}
__device__ __forceinline__ void mbar_wait(uint32_t a, int parity) {
    asm volatile(
        "{\n\t.reg .pred P;\n"
        "W%=:\n\t"
        "mbarrier.try_wait.parity.acquire.cta.shared::cta.b64 P, [%0], %1;\n\t"
        "@!P bra W%=;\n\t}"
        :: "r"(a), "r"(parity) : "memory");
}
__device__ __forceinline__ void tma_g2s(uint32_t smem_dst, const void* gsrc,
                                        int bytes, uint32_t mbar) {
    asm volatile(
        "cp.async.bulk.shared::cta.global.mbarrier::complete_tx::bytes "
        "[%0], [%1], %2, [%3];"
        :: "r"(smem_dst), "l"(gsrc), "r"(bytes), "r"(mbar) : "memory");
}
__device__ __forceinline__ void tma_s2g(void* gdst, uint32_t smem_src, int bytes) {
    asm volatile(
        "cp.async.bulk.global.shared::cta.bulk_group [%0], [%1], %2;"
        :: "l"(gdst), "r"(smem_src), "r"(bytes) : "memory");
}

__device__ __forceinline__ void push_direct(
    const int* __restrict__ cmask, const int* __restrict__ b32,
    bool is64, int idx, float s)
{
    if (cmask[idx]) {
        const int gph = is64 ? (int)((const long long*)b32)[idx] : b32[idx];
        const int p   = atomicAdd(&g_cand_cnt[gph], 1);
        if (p < CAP2) {
            g_cand_fl[gph * CAP2 + p] = flipf(s);
            g_cand_ix[gph * CAP2 + p] = idx;
        }
    }
}

// ---------------------------------------------------------------------------
// K1: fully TMA-driven streaming scan, 4-deep read pipeline.
//  - Reads: ALL of this block's score chunks are issued up-front into 4
//    static smem buffers (reads issued BEFORE fills: latency-critical).
//  - Fill: NEG_MIN pattern tile -> gmem via cp.async.bulk s2g.
//  - Warps scan smem; threshold hits -> smem queue; drain filters via cmask
//    and pushes to per-graph global candidate lists.
//  - Generic-E correctness: wait -> scan -> syncthreads -> reissue per stage.
// ---------------------------------------------------------------------------
__global__ void __launch_bounds__(BS) scan_kernel(
    const float* __restrict__ scores,
    const int*   __restrict__ cmask,        // bool delivered as int32
    const int*   __restrict__ b32,          // edge_batch (int32 or int64 words)
    float* __restrict__ out,
    int E)
{
    __shared__ int   q_cnt;
    __shared__ float q_sc[QCAP];
    __shared__ int   q_ix[QCAP];
    __shared__ __align__(16) float pat[FCHUNK_F];
    __shared__ __align__(16) float rbuf[NSTAGE][RCHUNK_F];
    __shared__ __align__(8)  unsigned long long mbar_sto[NSTAGE];

    const bool is64 = (b32[(E - 2) | 1] == 0);   // dtype sniff (L1-broadcast)
    const int  tid  = threadIdx.x;

    for (int i = tid; i < FCHUNK_F; i += BS) pat[i] = NEG_MIN;
    if (tid == 0) {
        q_cnt = 0;
        #pragma unroll
        for (int s = 0; s < NSTAGE; ++s) mbar_init(smem_u32(&mbar_sto[s]), 1);
    }
    __syncthreads();

    const uint32_t mb_base = smem_u32(&mbar_sto[0]);
    const uint32_t rb_base = smem_u32(&rbuf[0][0]);
    const uint32_t ps      = smem_u32(pat);

    const int nfc = E / FCHUNK_F;
    const int nrc = E / RCHUNK_F;

    // ---- Prologue: issue up to NSTAGE read chunks, then the fills ----
    if (tid == 0) {
        asm volatile("fence.proxy.async.shared::cta;" ::: "memory");
        #pragma unroll
        for (int s = 0; s < NSTAGE; ++s) {
            const int c = blockIdx.x + s * NBLK;
            if (c < nrc) {
                mbar_expect_tx(mb_base + s * 8, RCHUNK_F * 4);
                tma_g2s(rb_base + s * (RCHUNK_F * 4),
                        scores + (size_t)c * RCHUNK_F, RCHUNK_F * 4,
                        mb_base + s * 8);
            }
        }
        for (int c = blockIdx.x; c < nfc; c += NBLK)
            tma_s2g(out + (size_t)c * FCHUNK_F, ps, FCHUNK_F * 4);
        asm volatile("cp.async.bulk.commit_group;" ::: "memory");
    }
    if (blockIdx.x == 0) {                   // scalar fill beyond last fill chunk
        for (int i = nfc * FCHUNK_F + tid; i < E; i += BS) out[i] = NEG_MIN;
    }

    // ---- Pipelined smem scan ----
    for (int i = 0;; ++i) {
        const int c = blockIdx.x + i * NBLK;
        if (c >= nrc) break;
        const int st  = i & (NSTAGE - 1);
        const int par = (i / NSTAGE) & 1;

        mbar_wait(mb_base + st * 8, par);

        const float4* rb4 = (const float4*)&rbuf[st][0];
        const int base = c * RCHUNK_F;
        #pragma unroll
        for (int v = 0; v < RCHUNK_F / 4 / BS; ++v) {
            const int j = tid + v * BS;
            const float4 sc = rb4[j];
            const float  mx = fmaxf(fmaxf(sc.x, sc.y), fmaxf(sc.z, sc.w));
            if (mx > THR) {
                const int ib = base + (j << 2);
                #pragma unroll
                for (int w = 0; w < 4; ++w) {
                    const float s = (w == 0) ? sc.x : (w == 1) ? sc.y : (w == 2) ? sc.z : sc.w;
                    if (s > THR) {
                        const int p = atomicAdd(&q_cnt, 1);
                        if (p < QCAP) { q_sc[p] = s; q_ix[p] = ib + w; }
                        else          push_direct(cmask, b32, is64, ib + w, s);
                    }
                }
            }
        }

        // Reissue this stage for chunk c + NSTAGE*NBLK (generic-E path).
        const int cn = c + NSTAGE * NBLK;
        if (cn < nrc) {
            __syncthreads();                 // all reads of rbuf[st] done
            if (tid == 0) {
                mbar_expect_tx(mb_base + st * 8, RCHUNK_F * 4);
                tma_g2s(rb_base + st * (RCHUNK_F * 4),
                        scores + (size_t)cn * RCHUNK_F, RCHUNK_F * 4,
                        mb_base + st * 8);
            }
        }
    }

    // scalar score tail beyond the last read chunk
    if (blockIdx.x == 0) {
        for (int i = nrc * RCHUNK_F + tid; i < E; i += BS) {
            const float s = scores[i];
            if (s > THR) {
                const int p = atomicAdd(&q_cnt, 1);
                if (p < QCAP) { q_sc[p] = s; q_ix[p] = i; }
                else          push_direct(cmask, b32, is64, i, s);
            }
        }
    }
    __syncthreads();

    // ---- Drain: parallel mask filter + global push ----
    const int n = min(q_cnt, QCAP);
    for (int j = tid; j < n; j += BS) {
        const int idx = q_ix[j];
        if (cmask[idx]) {
            const int gph = is64 ? (int)((const long long*)b32)[idx] : b32[idx];
            const int p   = atomicAdd(&g_cand_cnt[gph], 1);
            if (p < CAP2) {
                g_cand_fl[gph * CAP2 + p] = flipf(q_sc[j]);
                g_cand_ix[gph * CAP2 + p] = idx;
            }
        }
    }
    __syncthreads();

    if (tid == 0)
        asm volatile("cp.async.bulk.wait_group 0;" ::: "memory");
}

// ---------------------------------------------------------------------------
// K2: per-graph exact top-K via byte-radix select in smem (stable tie-break:
// score desc, index asc); segmented log-denominator; kept writes. Exact gmem
// radix fallback when the candidate list is unusable.
// ---------------------------------------------------------------------------
__global__ void __launch_bounds__(BS) rank_kernel(
    const float* __restrict__ logits,
    const float* __restrict__ scores,
    const float* __restrict__ stop,
    const int*   __restrict__ cmask,
    const int*   __restrict__ b32,
    float* __restrict__ out,
    int E)
{
    __shared__ unsigned buf_fl[CAP];
    __shared__ int      buf_ix[CAP];
    __shared__ unsigned tb_fl[CAP2];
    __shared__ int      tb_ix[CAP2];
    __shared__ int      s_kidx[TOPK];
    __shared__ float    s_lv[TOPK];
    __shared__ float    s_ld;
    __shared__ int      seg[2];
    __shared__ int      hist[2048];
    __shared__ int      s_found, s_bin, s_above, s_minix, s_kcnt;
    __shared__ unsigned s_Tf;
    __shared__ int      s_Tix;

    const int g   = blockIdx.x;
    const int tid = threadIdx.x;
    const int cnt = g_cand_cnt[g];

    int kc;
    if (cnt >= TOPK && cnt <= CAP2) {
        for (int j = tid; j < cnt; j += BS) {
            buf_fl[j] = g_cand_fl[g * CAP2 + j];
            buf_ix[j] = g_cand_ix[g * CAP2 + j];
        }
        __syncthreads();

        unsigned prefix = 0, pmask = 0;
        int above = 0;
        for (int lvl = 0; lvl < 4; ++lvl) {
            const int shift = 24 - 8 * lvl;
            if (tid < 256) hist[tid] = 0;
            __syncthreads();
            for (int j = tid; j < cnt; j += BS) {
                const unsigned fl = buf_fl[j];
                if ((fl & pmask) == prefix)
                    atomicAdd(&hist[(fl >> shift) & 0xFF], 1);
            }
            __syncthreads();

            if (tid < 32) {
                const int lane = tid;
                const int Kp   = TOPK - above;
                int cum = 0;
                for (int base = 255; base >= 0; base -= 32) {
                    int bin = base - lane;
                    int c   = hist[bin];
                    int incl = c;
                    #pragma unroll
                    for (int off = 1; off < 32; off <<= 1) {
                        int v = __shfl_up_sync(0xffffffffu, incl, off);
                        if (lane >= off) incl += v;
                    }
                    unsigned bal = __ballot_sync(0xffffffffu, cum + incl >= Kp);
                    if (bal) {
                        int first = __ffs(bal) - 1;
                        if (lane == first) { s_bin = bin; s_above = cum + incl - c; }
                        break;
                    }
                    cum += __shfl_sync(0xffffffffu, incl, 31);
                }
            }
            __syncthreads();

            const int b = s_bin;
            const int n = hist[b];
            above  += s_above;
            prefix |= ((unsigned)b) << shift;
            pmask  |= 0xFFu << shift;
            __syncthreads();

            if (n <= 64 || lvl == 3) {
                if (tid == 0) s_kcnt = 0;
                __syncthreads();
                for (int j = tid; j < cnt; j += BS) {
                    const unsigned fl = buf_fl[j];
                    if ((fl & pmask) == prefix) {
                        int p = atomicAdd(&s_kcnt, 1);
                        tb_fl[p] = fl; tb_ix[p] = buf_ix[j];
                    }
                }
                __syncthreads();
                const int nn = s_kcnt;
                const int r  = TOPK - 1 - above;
                for (int j = tid; j < nn; j += BS) {
                    const unsigned fj = tb_fl[j];
                    const int      ij = tb_ix[j];
                    int rk = 0;
                    for (int l = 0; l < nn; ++l) {
                        const unsigned fl2 = tb_fl[l];
                        rk += (fl2 > fj) || (fl2 == fj && tb_ix[l] < ij);
                    }
                    if (rk == r) { s_Tf = fj; s_Tix = ij; }
                }
                __syncthreads();
                break;
            }
        }

        const unsigned Tf = s_Tf; const int Tix = s_Tix;
        if (tid == 0) s_kcnt = 0;
        __syncthreads();
        for (int j = tid; j < cnt; j += BS) {
            const unsigned fl = buf_fl[j];
            if (fl > Tf || (fl == Tf && buf_ix[j] <= Tix)) {
                int p = atomicAdd(&s_kcnt, 1);
                s_kidx[p] = buf_ix[j];
            }
        }
        kc = TOPK;
        __syncthreads();
    } else {
        if (tid < 2) {
            const int target = g + tid;
            int lo = 0;
            if (target == NGRAPH) lo = E;
            else if (target > 0) {
                const bool is64 = (b32[(E - 2) | 1] == 0);
                int hi = E;
                if (is64) {
                    const long long* b = (const long long*)b32;
                    const long long key = (long long)target;
                    while (lo < hi) { int mid = (lo + hi) >> 1; if (b[mid] < key) lo = mid + 1; else hi = mid; }
                } else {
                    while (lo < hi) { int mid = (lo + hi) >> 1; if (b32[mid] < target) lo = mid + 1; else hi = mid; }
                }
            }
            seg[tid] = lo;
        }
        __syncthreads();
        const int s0 = seg[0], s1 = seg[1];

        unsigned prefix = 0, pmask = 0;
        int  above = 0;
        bool keepall = false, have_thr = false;

        for (int lvl = 0; lvl < 3; ++lvl) {
            const int      shift = (lvl == 0) ? 21 : (lvl == 1) ? 10 : 0;
            const unsigned mw    = (lvl == 2) ? 0x3FFu : 0x7FFu;

            for (int j = tid; j < 2048; j += BS) hist[j] = 0;
            if (tid == 0) s_found = 0;
            __syncthreads();

            for (int i = s0 + tid; i < s1; i += BS) {
                if (cmask[i] != 0) {
                    unsigned fl = flipf(scores[i]);
                    if ((fl & pmask) == prefix)
                        atomicAdd(&hist[(fl >> shift) & mw], 1);
                }
            }
            __syncthreads();

            if (tid < 32) {
                const int lane = tid;
                const int Kp   = TOPK - above;
                int cum = 0;
                for (int base = (int)mw; base >= 0; base -= 32) {
                    int bin = base - lane;
                    int c   = (bin >= 0) ? hist[bin] : 0;
                    int incl = c;
                    #pragma unroll
                    for (int off = 1; off < 32; off <<= 1) {
                        int v = __shfl_up_sync(0xffffffffu, incl, off);
                        if (lane >= off) incl += v;
                    }
                    unsigned bal = __ballot_sync(0xffffffffu, cum + incl >= Kp);
                    if (bal) {
                        int first = __ffs(bal) - 1;
                        if (lane == first) { s_bin = bin; s_above = cum + incl - c; s_found = 1; }
                        break;
                    }
                    cum += __shfl_sync(0xffffffffu, incl, 31);
                }
            }
            __syncthreads();

            if (!s_found) { keepall = true; break; }

            const int b = s_bin;
            above  += s_above;
            const int n = hist[b];
            prefix |= ((unsigned)b) << shift;
            pmask  |= mw << shift;
            __syncthreads();

            if (n <= CAP) {
                if (tid == 0) s_kcnt = 0;
                __syncthreads();
                for (int i = s0 + tid; i < s1; i += BS) {
                    if (cmask[i] != 0) {
                        unsigned fl = flipf(scores[i]);
                        if ((fl & pmask) == prefix) {
                            int p = atomicAdd(&s_kcnt, 1);
                            buf_fl[p] = fl; buf_ix[p] = i;
                        }
                    }
                }
                __syncthreads();
                const int nn = s_kcnt;
                const int r  = TOPK - 1 - above;
                for (int j = tid; j < nn; j += BS) {
                    unsigned fj = buf_fl[j]; int ij = buf_ix[j];
                    int rk = 0;
                    for (int l = 0; l < nn; ++l) {
                        unsigned fl2 = buf_fl[l];
                        rk += (fl2 > fj) || (fl2 == fj && buf_ix[l] < ij);
                    }
                    if (rk == r) { s_Tf = fj; s_Tix = ij; }
                }
                have_thr = true;
                __syncthreads();
                break;
            }
        }

        unsigned Tf; int Tix;
        if (keepall)       { Tf = 0u;   Tix = 0x7FFFFFFF; }
        else if (have_thr) { Tf = s_Tf; Tix = s_Tix; }
        else {
            const int m = TOPK - above;
            int last = -1;
            for (int t = 0; t < m; ++t) {
                if (tid == 0) s_minix = 0x7FFFFFFF;
                __syncthreads();
                for (int i = s0 + tid; i < s1; i += BS) {
                    if (cmask[i] != 0 && i > last) {
                        if (flipf(scores[i]) == prefix) atomicMin(&s_minix, i);
                    }
                }
                __syncthreads();
                last = s_minix;
                __syncthreads();
            }
            Tf = prefix; Tix = last;
        }

        if (tid == 0) s_kcnt = 0;
        __syncthreads();
        for (int i = s0 + tid; i < s1; i += BS) {
            if (cmask[i] != 0) {
                unsigned fl = flipf(scores[i]);
                if (fl > Tf || (fl == Tf && i <= Tix)) {
                    int p = atomicAdd(&s_kcnt, 1);
                    if (p < TOPK) s_kidx[p] = i;
                }
            }
        }
        __syncthreads();
        kc = min(s_kcnt, TOPK);
    }

    // ---- Segmented log-denominator over the <=32 kept logits + stop ----
    if (tid < kc) s_lv[tid] = logits[s_kidx[tid]];   // TEMP == 1.0
    __syncthreads();

    if (tid < 32) {
        float v = (tid < kc) ? s_lv[tid] : -INFINITY;
        float mx = v;
        #pragma unroll
        for (int off = 16; off; off >>= 1) mx = fmaxf(mx, __shfl_xor_sync(0xffffffffu, mx, off));
        float e = (tid < kc) ? expf(v - mx) : 0.0f;
        #pragma unroll
        for (int off = 16; off; off >>= 1) e += __shfl_xor_sync(0xffffffffu, e, off);
        if (tid == 0) {
            float st = stop[g];
            float ld;
            if (kc == 0) ld = st;
            else {
                float lse = logf(e) + mx;
                float a = fmaxf(lse, st), b2 = fminf(lse, st);
                ld = a + log1pf(expf(b2 - a));
            }
            s_ld = ld;
        }
    }
    __syncthreads();

    if (tid < kc) out[s_kidx[tid]] = s_lv[tid] - s_ld;

    if (tid == 0) g_cand_cnt[g] = 0;
}

extern "C" void kernel_launch(void* const* d_in, const int* in_sizes, int n_in,
                              void* d_out, int out_size) {
    const float* logits = (const float*)d_in[0];
    const float* scores = (const float*)d_in[1];
    const float* stop   = (const float*)d_in[2];
    const int*   batch  = (const int*)d_in[3];
    const int*   cmask  = (const int*)d_in[4];
    float* out = (float*)d_out;
    const int E = in_sizes[0];

    scan_kernel<<<NBLK, BS>>>(scores, cmask, batch, out, E);
    rank_kernel<<<NGRAPH, BS>>>(logits, scores, stop, cmask, batch, out, E);
}